// round 12
// baseline (speedup 1.0000x reference)
#include <cuda_runtime.h>

#define BB   16
#define NN   4096
#define DD   64
#define NPT  1024
#define NSM  32
#define TOT  (BB*NPT*NSM)          // 524288 samples
#define CNT_INV (1.0f/524288.0f)

typedef unsigned long long u64;

// ---------------- f32x2 packed helpers ----------------
__device__ __forceinline__ u64 pk(float lo, float hi) {
    u64 r; asm("mov.b64 %0, {%1,%2};" : "=l"(r) : "f"(lo), "f"(hi)); return r;
}
__device__ __forceinline__ void upk(float& lo, float& hi, u64 v) {
    asm("mov.b64 {%0,%1}, %2;" : "=f"(lo), "=f"(hi) : "l"(v));
}
__device__ __forceinline__ void fma2(u64& d, u64 a, u64 b, u64 c) {
    asm("fma.rn.f32x2 %0, %1, %2, %3;" : "=l"(d) : "l"(a), "l"(b), "l"(c));
}
__device__ __forceinline__ void add2(u64& d, u64 a, u64 b) {
    asm("add.rn.f32x2 %0, %1, %2;" : "=l"(d) : "l"(a), "l"(b));
}
__device__ __forceinline__ void mul2(u64& d, u64 a, u64 b) {
    asm("mul.rn.f32x2 %0, %1, %2;" : "=l"(d) : "l"(a), "l"(b));
}

__device__ __forceinline__ unsigned ordf(float x) {
    unsigned u = __float_as_uint(x);
    return (u & 0x80000000u) ? ~u : (u | 0x80000000u);
}
__device__ __forceinline__ float unordf(unsigned u) {
    return (u & 0x80000000u) ? __uint_as_float(u & 0x7fffffffu) : __uint_as_float(~u);
}

// ---------------- device scratch ----------------
__device__ int   g_fps[BB*NPT];
__device__ int   g_ball[BB*NPT*NSM];
__device__ float g_y1[(size_t)64*TOT];   // [channel][sample]
__device__ float g_y2[(size_t)64*TOT];   // [channel][sample]
__device__ float g_ymax[BB*NPT*128];
__device__ float g_stats[512];           // L1 sum@0 sq@64 | L2 sum@128 sq@192 | L3 sum@256 sq@384

__global__ void zero_stats_kernel() {
    int t = threadIdx.x;
    if (t < 512) g_stats[t] = 0.0f;
}

__device__ __forceinline__ void bn_aff(float sum, float sq, float g, float beta,
                                       float& s, float& h) {
    float mean = sum * CNT_INV;
    float var  = sq  * CNT_INV - mean*mean;
    float inv  = rsqrtf(var + 1e-5f);
    s = g * inv;
    h = beta - mean*s;
}

// ---------------- FPS: 1 block/batch, 1 barrier/iter, redux argmax ----------------
__global__ void __launch_bounds__(512, 1)
fps_kernel(const float* __restrict__ xyz) {
    extern __shared__ float sh[];
    float* xs = sh; float* ys = sh + NN; float* zs = sh + 2*NN;
    u64* keys = (u64*)(sh + 3*NN);
    int b = blockIdx.x, tid = threadIdx.x, lane = tid & 31, w = tid >> 5;
    const float* xp = xyz + (size_t)b*NN*3;
    for (int t = tid; t < NN*3; t += 512) {
        float v = xp[t]; int i = t/3, c = t - 3*i;
        if (c == 0) xs[i] = v; else if (c == 1) ys[i] = v; else zs[i] = v;
    }
    __syncthreads();

    float px[8], py[8], pz[8];
    #pragma unroll
    for (int p = 0; p < 8; p++) {
        int i = tid + 512*p;
        px[p] = xs[i]; py[p] = ys[i]; pz[p] = zs[i];
    }
    u64 X[4], Y[4], Z[4], D2[4];
    #pragma unroll
    for (int q = 0; q < 4; q++) {
        X[q] = pk(px[2*q], px[2*q+1]);
        Y[q] = pk(py[2*q], py[2*q+1]);
        Z[q] = pk(pz[2*q], pz[2*q+1]);
        D2[q] = pk(1e10f, 1e10f);
    }

    int far = 0;
    for (int j = 0; j < NPT; j++) {
        if (tid == 0) g_fps[b*NPT + j] = far;
        float cx = xs[far], cy = ys[far], cz = zs[far];
        u64 ncx = pk(-cx,-cx), ncy = pk(-cy,-cy), ncz = pk(-cz,-cz);
        float bv = -1.0f; int bi = 0;
        #pragma unroll
        for (int q = 0; q < 4; q++) {
            u64 dx, dy, dz, s2;
            add2(dx, X[q], ncx);
            add2(dy, Y[q], ncy);
            add2(dz, Z[q], ncz);
            mul2(dx, dx, dx); mul2(dy, dy, dy); mul2(dz, dz, dz);
            add2(s2, dx, dy); add2(s2, s2, dz);
            float s0, s1, d0, d1;
            upk(s0, s1, s2); upk(d0, d1, D2[q]);
            d0 = fminf(d0, s0); d1 = fminf(d1, s1);
            D2[q] = pk(d0, d1);
            int i0 = tid + 1024*q, i1 = i0 + 512;
            if (d0 > bv) { bv = d0; bi = i0; }
            if (d1 > bv) { bv = d1; bi = i1; }
        }
        unsigned kv = ordf(bv);
        unsigned vmax = __reduce_max_sync(0xffffffffu, kv);
        unsigned iw = (kv == vmax) ? (unsigned)bi : 0xffffffffu;
        unsigned imin = __reduce_min_sync(0xffffffffu, iw);
        if (lane == 0)
            keys[(j & 1)*16 + w] = ((u64)vmax << 32) | (u64)(unsigned)(~imin);
        __syncthreads();
        const u64* kb = keys + (j & 1)*16;
        u64 kk = kb[0];
        #pragma unroll
        for (int t = 1; t < 16; t++) { u64 o = kb[t]; if (o > kk) kk = o; }
        far = (int)(~(unsigned)kk);
    }
}

// ---------------- ball query ----------------
__global__ void ball_kernel(const float* __restrict__ xyz, float* __restrict__ out) {
    extern __shared__ float sh[];
    float* xs = sh; float* ys = sh + NN; float* zs = sh + 2*NN; float* nn = sh + 3*NN;
    int blk = blockIdx.x, tid = threadIdx.x;
    int b = blk >> 3, cbase = (blk & 7) * 128;
    const float* xp = xyz + (size_t)b*NN*3;
    for (int t = tid; t < NN*3; t += 512) {
        float v = xp[t]; int i = t/3, c = t - 3*i;
        if (c == 0) xs[i] = v; else if (c == 1) ys[i] = v; else zs[i] = v;
    }
    __syncthreads();
    for (int i = tid; i < NN; i += 512)
        nn[i] = __fadd_rn(__fadd_rn(__fmul_rn(xs[i],xs[i]), __fmul_rn(ys[i],ys[i])), __fmul_rn(zs[i],zs[i]));
    __syncthreads();

    int w = tid >> 5, lane = tid & 31;
    const float r2 = 0.04f;
    for (int jj = w; jj < 128; jj += 16) {
        int j = cbase + jj;
        int fidx = g_fps[b*NPT + j];
        float cx = xs[fidx], cy = ys[fidx], cz = zs[fidx], cn = nn[fidx];
        if (lane == 0) {
            float* o = out + (size_t)(b*NPT + j)*3;
            o[0] = cx; o[1] = cy; o[2] = cz;
        }
        int cnt = 0, first = -1;
        int* bo = g_ball + (size_t)(b*NPT + j)*NSM;
        for (int base = 0; base < NN; base += 32) {
            int i = base + lane;
            float dot = __fadd_rn(__fadd_rn(__fmul_rn(cx,xs[i]), __fmul_rn(cy,ys[i])), __fmul_rn(cz,zs[i]));
            float sq  = __fadd_rn(__fadd_rn(__fmul_rn(-2.0f,dot), cn), nn[i]);
            bool ok = (sq <= r2);
            unsigned m = __ballot_sync(0xffffffffu, ok);
            if (first < 0 && m) first = base + __ffs(m) - 1;
            int pos = cnt + __popc(m & ((1u << lane) - 1u));
            if (ok && pos < NSM) bo[pos] = i;
            cnt += __popc(m);
            if (cnt >= NSM) break;
        }
        if (cnt < NSM && lane >= cnt) bo[lane] = first;
    }
}

// ============ tiled GEMM: thread = 8 samples (4 f32x2 pairs) x 8 channels, prefetched ========
#define GEMM_LOOP(K, NWID, AOFF_EXPR)                                          \
    u64 acc[8][4];                                                             \
    _Pragma("unroll")                                                          \
    for (int c = 0; c < 8; c++) { acc[c][0]=0; acc[c][1]=0; acc[c][2]=0; acc[c][3]=0; } \
    ulonglong2 av0, av1; float4 wq0, wq1;                                      \
    {                                                                          \
        const int k = 0; int aoff = (AOFF_EXPR);                               \
        av0 = *(const ulonglong2*)(As + aoff);                                 \
        av1 = *(const ulonglong2*)(As + aoff + 4);                             \
        wq0 = *(const float4*)(Ws + tn*4);                                     \
        wq1 = *(const float4*)(Ws + (NWID)/2 + tn*4);                          \
    }                                                                          \
    _Pragma("unroll 4")                                                        \
    for (int kk = 0; kk < (K); kk++) {                                         \
        u64 a0 = av0.x, a1 = av0.y, a2 = av1.x, a3 = av1.y;                    \
        float wfv[8] = {wq0.x,wq0.y,wq0.z,wq0.w,wq1.x,wq1.y,wq1.z,wq1.w};      \
        if (kk + 1 < (K)) {                                                    \
            const int k = kk + 1; int aoff = (AOFF_EXPR);                      \
            av0 = *(const ulonglong2*)(As + aoff);                             \
            av1 = *(const ulonglong2*)(As + aoff + 4);                         \
            wq0 = *(const float4*)(Ws + k*(NWID) + tn*4);                      \
            wq1 = *(const float4*)(Ws + k*(NWID) + (NWID)/2 + tn*4);           \
        }                                                                      \
        _Pragma("unroll")                                                      \
        for (int c = 0; c < 8; c++) {                                          \
            u64 wd = pk(wfv[c], wfv[c]);                                       \
            fma2(acc[c][0], wd, a0, acc[c][0]);                                \
            fma2(acc[c][1], wd, a1, acc[c][1]);                                \
            fma2(acc[c][2], wd, a2, acc[c][2]);                                \
            fma2(acc[c][3], wd, a3, acc[c][3]);                                \
        }                                                                      \
    }

// W interleaved position for channel n within a row of width NWID
__device__ __forceinline__ int wpos(int n, int nwid) {
    return ((n >> 2) & 1) * (nwid >> 1) + (n >> 3) * 4 + (n & 3);
}

// ---------------- conv1: cooperative gather + 67->64, M-tile 128, 128 thr, 4 CTAs/SM --------
__global__ void __launch_bounds__(128, 4)
conv1_kernel(const float* __restrict__ xyz, const float* __restrict__ pts,
             const float* __restrict__ w1,  const float* __restrict__ b1,
             const float* __restrict__ nxyz) {
    extern __shared__ float sh[];
    float* As   = sh;              // 68*128 (rows k, 32B granules XOR-swizzled)
    float* Ws   = As + 68*128;     // 68*64 interleaved
    float* bs   = Ws + 68*64;
    float* ssum = bs + 64;
    float* ssq  = ssum + 64;
    int tid = threadIdx.x;
    for (int t = tid; t < 64*67; t += 128) { int n = t/67, k = t - n*67; Ws[k*64 + wpos(n,64)] = w1[t]; }
    if (tid < 64) { bs[tid] = b1[tid]; ssum[tid] = 0.f; ssq[tid] = 0.f; }

    int s0 = blockIdx.x*128;
    {   // rows 0..2: one thread per sample
        int s = s0 + tid;
        int bj = s >> 5, b = s >> 15;
        int idx = g_ball[s];
        const float* xp = xyz  + (size_t)(b*NN + idx)*3;
        const float* cp = nxyz + (size_t)bj*3;
        As[0*128 + tid] = xp[0]-cp[0];
        As[1*128 + tid] = xp[1]-cp[1];
        As[2*128 + tid] = xp[2]-cp[2];
    }
    {   // rows 3..66: 8 threads/sample, 32B contiguous each, XOR-swizzled STS
        int w = tid >> 5, lane = tid & 31;
        int chunk = lane & 7, sg = lane >> 3;
        #pragma unroll
        for (int p = 0; p < 8; p++) {
            int sl = p*16 + w*4 + sg;
            int s = s0 + sl;
            int b = s >> 15;
            int idx = g_ball[s];
            const float4* pp = (const float4*)(pts + (size_t)(b*NN + idx)*64) + chunk*2;
            float4 v0 = pp[0], v1 = pp[1];
            int g = sl >> 3, slow = sl & 7;
            float vv[8] = {v0.x,v0.y,v0.z,v0.w,v1.x,v1.y,v1.z,v1.w};
            #pragma unroll
            for (int jj = 0; jj < 8; jj++) {
                int k = 3 + chunk*8 + jj;
                int gp = g ^ ((k >> 3) & 3);
                As[k*128 + gp*8 + slow] = vv[jj];
            }
        }
    }
    __syncthreads();

    int tn = tid & 7, tm = tid >> 3;       // tm 0..15, granule m0 = 8*tm
    int n0 = tn*8, m0 = tm*8;
    GEMM_LOOP(67, 64, k*128 + ((tm ^ ((k>>3)&3)) << 3))

    int lane = tid & 31;
    float sn[8], qn[8];
    #pragma unroll
    for (int c = 0; c < 8; c++) {
        u64 bd = pk(bs[n0+c], bs[n0+c]);
        add2(acc[c][0], acc[c][0], bd); add2(acc[c][1], acc[c][1], bd);
        add2(acc[c][2], acc[c][2], bd); add2(acc[c][3], acc[c][3], bd);
        float y0,y1,y2,y3,y4,y5,y6,y7;
        upk(y0,y1,acc[c][0]); upk(y2,y3,acc[c][1]);
        upk(y4,y5,acc[c][2]); upk(y6,y7,acc[c][3]);
        sn[c] = ((y0+y1)+(y2+y3)) + ((y4+y5)+(y6+y7));
        qn[c] = y0*y0+y1*y1+y2*y2+y3*y3+y4*y4+y5*y5+y6*y6+y7*y7;
        float* gp = g_y1 + (size_t)(n0+c)*TOT + s0 + m0;
        *(float4*)gp     = make_float4(y0,y1,y2,y3);
        *(float4*)(gp+4) = make_float4(y4,y5,y6,y7);
    }
    #pragma unroll
    for (int off = 8; off <= 16; off <<= 1)
        #pragma unroll
        for (int c = 0; c < 8; c++) {
            sn[c] += __shfl_xor_sync(0xffffffffu, sn[c], off);
            qn[c] += __shfl_xor_sync(0xffffffffu, qn[c], off);
        }
    if (lane < 8) {
        #pragma unroll
        for (int c = 0; c < 8; c++) {
            atomicAdd(&ssum[n0+c], sn[c]);
            atomicAdd(&ssq[n0+c],  qn[c]);
        }
    }
    __syncthreads();
    if (tid < 64) {
        atomicAdd(&g_stats[tid],      ssum[tid]);
        atomicAdd(&g_stats[64 + tid], ssq[tid]);
    }
}

// ---------------- conv2: BN1 folded, 64->64, M-tile 128, 128 thr, 4 CTAs/SM ----------------
__global__ void __launch_bounds__(128, 4)
conv2_kernel(const float* __restrict__ w2, const float* __restrict__ b2,
             const float* __restrict__ g1, const float* __restrict__ be1) {
    extern __shared__ float sh[];
    float* As   = sh;              // 64*128
    float* Ws   = As + 64*128;     // 64*64 interleaved
    float* sc   = Ws + 64*64;
    float* sf   = sc + 64;
    float* bs   = sf + 64;
    float* ssum = bs + 64;
    float* ssq  = ssum + 64;
    int tid = threadIdx.x;
    for (int t = tid; t < 64*64; t += 128) { int n = t >> 6, k = t & 63; Ws[k*64 + wpos(n,64)] = w2[t]; }
    if (tid < 64) {
        float s, h;
        bn_aff(g_stats[tid], g_stats[64 + tid], g1[tid], be1[tid], s, h);
        sc[tid] = s; sf[tid] = h;
        bs[tid] = b2[tid]; ssum[tid] = 0.f; ssq[tid] = 0.f;
    }
    __syncthreads();

    int s0 = blockIdx.x*128;
    {
        int col = (tid & 31) * 4, r0 = tid >> 5;
        #pragma unroll
        for (int r = r0; r < 64; r += 4) {
            float4 v = *(const float4*)(g_y1 + (size_t)r*TOT + s0 + col);
            float a = sc[r], b = sf[r];
            v.x = fmaxf(fmaf(v.x, a, b), 0.f);
            v.y = fmaxf(fmaf(v.y, a, b), 0.f);
            v.z = fmaxf(fmaf(v.z, a, b), 0.f);
            v.w = fmaxf(fmaf(v.w, a, b), 0.f);
            *(float4*)(As + r*128 + col) = v;
        }
    }
    __syncthreads();

    int tn = tid & 7, tm = tid >> 3;
    int n0 = tn*8, m0 = tm*8;
    GEMM_LOOP(64, 64, k*128 + m0)

    int lane = tid & 31;
    float sn[8], qn[8];
    #pragma unroll
    for (int c = 0; c < 8; c++) {
        u64 bd = pk(bs[n0+c], bs[n0+c]);
        add2(acc[c][0], acc[c][0], bd); add2(acc[c][1], acc[c][1], bd);
        add2(acc[c][2], acc[c][2], bd); add2(acc[c][3], acc[c][3], bd);
        float y0,y1,y2,y3,y4,y5,y6,y7;
        upk(y0,y1,acc[c][0]); upk(y2,y3,acc[c][1]);
        upk(y4,y5,acc[c][2]); upk(y6,y7,acc[c][3]);
        sn[c] = ((y0+y1)+(y2+y3)) + ((y4+y5)+(y6+y7));
        qn[c] = y0*y0+y1*y1+y2*y2+y3*y3+y4*y4+y5*y5+y6*y6+y7*y7;
        float* gp = g_y2 + (size_t)(n0+c)*TOT + s0 + m0;
        *(float4*)gp     = make_float4(y0,y1,y2,y3);
        *(float4*)(gp+4) = make_float4(y4,y5,y6,y7);
    }
    #pragma unroll
    for (int off = 8; off <= 16; off <<= 1)
        #pragma unroll
        for (int c = 0; c < 8; c++) {
            sn[c] += __shfl_xor_sync(0xffffffffu, sn[c], off);
            qn[c] += __shfl_xor_sync(0xffffffffu, qn[c], off);
        }
    if (lane < 8) {
        #pragma unroll
        for (int c = 0; c < 8; c++) {
            atomicAdd(&ssum[n0+c], sn[c]);
            atomicAdd(&ssq[n0+c],  qn[c]);
        }
    }
    __syncthreads();
    if (tid < 64) {
        atomicAdd(&g_stats[128 + tid], ssum[tid]);
        atomicAdd(&g_stats[192 + tid], ssq[tid]);
    }
}

// ---------------- conv3: BN2 folded, 64->128, M-tile 64, N=128, 128 thr, 4 CTAs/SM ----------
__global__ void __launch_bounds__(128, 4)
conv3_kernel(const float* __restrict__ w3, const float* __restrict__ b3,
             const float* __restrict__ g2, const float* __restrict__ be2) {
    extern __shared__ float sh[];
    float* As   = sh;              // 64*64
    float* Ws   = As + 64*64;      // 64*128 interleaved
    float* sc   = Ws + 64*128;
    float* sf   = sc + 64;
    float* bs   = sf + 64;
    float* ssum = bs + 128;
    float* ssq  = ssum + 128;
    unsigned* smax = (unsigned*)(ssq + 128);   // 2 groups * 128 ch
    int tid = threadIdx.x;
    for (int t = tid; t < 128*64; t += 128) {
        int n = t >> 6, k = t & 63;
        Ws[k*128 + wpos(n,128)] = w3[t];
    }
    if (tid < 64)  {
        float s, h;
        bn_aff(g_stats[128 + tid], g_stats[192 + tid], g2[tid], be2[tid], s, h);
        sc[tid] = s; sf[tid] = h;
    }
    if (tid < 128) { bs[tid] = b3[tid]; ssum[tid] = 0.f; ssq[tid] = 0.f; }
    for (int t = tid; t < 256; t += 128) smax[t] = 0u;
    __syncthreads();

    int s0 = blockIdx.x*64;
    {
        int col = (tid & 15) * 4, r0 = tid >> 4;
        #pragma unroll
        for (int r = r0; r < 64; r += 8) {
            float4 v = *(const float4*)(g_y2 + (size_t)r*TOT + s0 + col);
            float a = sc[r], b = sf[r];
            v.x = fmaxf(fmaf(v.x, a, b), 0.f);
            v.y = fmaxf(fmaf(v.y, a, b), 0.f);
            v.z = fmaxf(fmaf(v.z, a, b), 0.f);
            v.w = fmaxf(fmaf(v.w, a, b), 0.f);
            *(float4*)(As + r*64 + col) = v;
        }
    }
    __syncthreads();

    int tn = tid & 15, tm = tid >> 4;      // tn 0..15 (128 ch), tm 0..7, granule m0 = 8*tm
    int n0 = tn*8, m0 = tm*8;
    GEMM_LOOP(64, 128, k*64 + m0)

    int lane = tid & 31;
    int w = tid >> 5;
    int g = w >> 1;                        // pool group (32 samples): warps {0,1}->0, {2,3}->1
    float sn[8], qn[8], mx[8];
    #pragma unroll
    for (int c = 0; c < 8; c++) {
        u64 bd = pk(bs[n0+c], bs[n0+c]);
        add2(acc[c][0], acc[c][0], bd); add2(acc[c][1], acc[c][1], bd);
        add2(acc[c][2], acc[c][2], bd); add2(acc[c][3], acc[c][3], bd);
        float y0,y1,y2,y3,y4,y5,y6,y7;
        upk(y0,y1,acc[c][0]); upk(y2,y3,acc[c][1]);
        upk(y4,y5,acc[c][2]); upk(y6,y7,acc[c][3]);
        sn[c] = ((y0+y1)+(y2+y3)) + ((y4+y5)+(y6+y7));
        qn[c] = y0*y0+y1*y1+y2*y2+y3*y3+y4*y4+y5*y5+y6*y6+y7*y7;
        mx[c] = fmaxf(fmaxf(fmaxf(y0,y1),fmaxf(y2,y3)), fmaxf(fmaxf(y4,y5),fmaxf(y6,y7)));
    }
    #pragma unroll
    for (int c = 0; c < 8; c++) {
        sn[c] += __shfl_xor_sync(0xffffffffu, sn[c], 16);
        qn[c] += __shfl_xor_sync(0xffffffffu, qn[c], 16);
        mx[c]  = fmaxf(mx[c], __shfl_xor_sync(0xffffffffu, mx[c], 16));
    }
    if (lane < 16) {
        #pragma unroll
        for (int c = 0; c < 8; c++) {
            atomicAdd(&ssum[n0+c], sn[c]);
            atomicAdd(&ssq[n0+c],  qn[c]);
            atomicMax(&smax[g*128 + n0 + c], ordf(mx[c]));
        }
    }
    __syncthreads();
    if (tid < 128) {
        atomicAdd(&g_stats[256 + tid], ssum[tid]);
        atomicAdd(&g_stats[384 + tid], ssq[tid]);
    }
    for (int t = tid; t < 256; t += 128) {
        int gg = t >> 7, n = t & 127;
        int bj = blockIdx.x*2 + gg;
        g_ymax[bj*128 + n] = unordf(smax[t]);
    }
}

// ---------------- output: BN3 folded (monotone affine + ReLU on per-channel max) ------------
__global__ void out_kernel(float* __restrict__ out,
                           const float* __restrict__ g3, const float* __restrict__ be3) {
    int i = blockIdx.x*blockDim.x + threadIdx.x;
    if (i < BB*NPT*128) {
        int c = i & 127;
        float s, h;
        bn_aff(g_stats[256 + c], g_stats[384 + c], g3[c], be3[c], s, h);
        float v = fmaf(g_ymax[i], s, h);
        out[BB*NPT*3 + i] = fmaxf(v, 0.0f);
    }
}

extern "C" void kernel_launch(void* const* d_in, const int* in_sizes, int n_in,
                              void* d_out, int out_size) {
    const float* xyz = (const float*)d_in[0];
    const float* pts = (const float*)d_in[1];
    const float* w1  = (const float*)d_in[2];
    const float* b1  = (const float*)d_in[3];
    const float* g1  = (const float*)d_in[4];
    const float* be1 = (const float*)d_in[5];
    const float* w2  = (const float*)d_in[6];
    const float* b2  = (const float*)d_in[7];
    const float* g2  = (const float*)d_in[8];
    const float* be2 = (const float*)d_in[9];
    const float* w3  = (const float*)d_in[10];
    const float* b3  = (const float*)d_in[11];
    const float* g3  = (const float*)d_in[12];
    const float* be3 = (const float*)d_in[13];
    float* out = (float*)d_out;

    const int FPS_SMEM   = 3*NN*4 + 32*8;
    const int BALL_SMEM  = 4*NN*4;
    const int CONV1_SMEM = (68*128 + 68*64 + 64*3)*4;              // ~53 KB -> 4 CTAs
    const int CONV2_SMEM = (64*128 + 64*64 + 64*5)*4;              // ~50 KB -> 4 CTAs
    const int CONV3_SMEM = (64*64 + 64*128 + 64*2 + 128*3 + 256)*4;// ~52 KB -> 4 CTAs

    cudaFuncSetAttribute(fps_kernel,   cudaFuncAttributeMaxDynamicSharedMemorySize, FPS_SMEM);
    cudaFuncSetAttribute(ball_kernel,  cudaFuncAttributeMaxDynamicSharedMemorySize, BALL_SMEM);
    cudaFuncSetAttribute(conv1_kernel, cudaFuncAttributeMaxDynamicSharedMemorySize, CONV1_SMEM);
    cudaFuncSetAttribute(conv2_kernel, cudaFuncAttributeMaxDynamicSharedMemorySize, CONV2_SMEM);
    cudaFuncSetAttribute(conv3_kernel, cudaFuncAttributeMaxDynamicSharedMemorySize, CONV3_SMEM);

    zero_stats_kernel<<<1, 512>>>();
    fps_kernel<<<BB, 512, FPS_SMEM>>>(xyz);
    ball_kernel<<<BB*8, 512, BALL_SMEM>>>(xyz, out);
    conv1_kernel<<<TOT/128, 128, CONV1_SMEM>>>(xyz, pts, w1, b1, out);
    conv2_kernel<<<TOT/128, 128, CONV2_SMEM>>>(w2, b2, g1, be1);
    conv3_kernel<<<TOT/64, 128, CONV3_SMEM>>>(w3, b3, g2, be2);
    out_kernel<<<(BB*NPT*128 + 255)/256, 256>>>(out, g3, be3);
}

// round 13
// speedup vs baseline: 1.0966x; 1.0966x over previous
#include <cuda_runtime.h>

#define BB   16
#define NN   4096
#define DD   64
#define NPT  1024
#define NSM  32
#define TOT  (BB*NPT*NSM)          // 524288 samples
#define CNT_INV (1.0f/524288.0f)

typedef unsigned long long u64;

// ---------------- f32x2 packed helpers ----------------
__device__ __forceinline__ u64 pk(float lo, float hi) {
    u64 r; asm("mov.b64 %0, {%1,%2};" : "=l"(r) : "f"(lo), "f"(hi)); return r;
}
__device__ __forceinline__ void upk(float& lo, float& hi, u64 v) {
    asm("mov.b64 {%0,%1}, %2;" : "=f"(lo), "=f"(hi) : "l"(v));
}
__device__ __forceinline__ void fma2(u64& d, u64 a, u64 b, u64 c) {
    asm("fma.rn.f32x2 %0, %1, %2, %3;" : "=l"(d) : "l"(a), "l"(b), "l"(c));
}
__device__ __forceinline__ void add2(u64& d, u64 a, u64 b) {
    asm("add.rn.f32x2 %0, %1, %2;" : "=l"(d) : "l"(a), "l"(b));
}
__device__ __forceinline__ void mul2(u64& d, u64 a, u64 b) {
    asm("mul.rn.f32x2 %0, %1, %2;" : "=l"(d) : "l"(a), "l"(b));
}

__device__ __forceinline__ unsigned ordf(float x) {
    unsigned u = __float_as_uint(x);
    return (u & 0x80000000u) ? ~u : (u | 0x80000000u);
}
__device__ __forceinline__ float unordf(unsigned u) {
    return (u & 0x80000000u) ? __uint_as_float(u & 0x7fffffffu) : __uint_as_float(~u);
}

// ---------------- device scratch ----------------
__device__ int   g_fps[BB*NPT];
__device__ int   g_ball[BB*NPT*NSM];
__device__ float g_y1[(size_t)64*TOT];   // [channel][sample]
__device__ float g_y2[(size_t)64*TOT];   // [channel][sample]
__device__ float g_ymax[BB*NPT*128];
__device__ float g_stats[512];           // L1 sum@0 sq@64 | L2 sum@128 sq@192 | L3 sum@256 sq@384

__global__ void zero_stats_kernel() {
    int t = threadIdx.x;
    if (t < 512) g_stats[t] = 0.0f;
}

__device__ __forceinline__ void bn_aff(float sum, float sq, float g, float beta,
                                       float& s, float& h) {
    float mean = sum * CNT_INV;
    float var  = sq  * CNT_INV - mean*mean;
    float inv  = rsqrtf(var + 1e-5f);
    s = g * inv;
    h = beta - mean*s;
}

// ---------------- FPS: 1 block/batch, 1 barrier/iter, redux argmax, tree block-reduce -------
__global__ void __launch_bounds__(512, 1)
fps_kernel(const float* __restrict__ xyz) {
    extern __shared__ float sh[];
    float* xs = sh; float* ys = sh + NN; float* zs = sh + 2*NN;
    u64* keys = (u64*)(sh + 3*NN);
    int b = blockIdx.x, tid = threadIdx.x, lane = tid & 31, w = tid >> 5;
    const float* xp = xyz + (size_t)b*NN*3;
    for (int t = tid; t < NN*3; t += 512) {
        float v = xp[t]; int i = t/3, c = t - 3*i;
        if (c == 0) xs[i] = v; else if (c == 1) ys[i] = v; else zs[i] = v;
    }
    __syncthreads();

    float px[8], py[8], pz[8];
    #pragma unroll
    for (int p = 0; p < 8; p++) {
        int i = tid + 512*p;
        px[p] = xs[i]; py[p] = ys[i]; pz[p] = zs[i];
    }
    u64 X[4], Y[4], Z[4], D2[4];
    #pragma unroll
    for (int q = 0; q < 4; q++) {
        X[q] = pk(px[2*q], px[2*q+1]);
        Y[q] = pk(py[2*q], py[2*q+1]);
        Z[q] = pk(pz[2*q], pz[2*q+1]);
        D2[q] = pk(1e10f, 1e10f);
    }

    int far = 0;
    for (int j = 0; j < NPT; j++) {
        if (tid == 0) g_fps[b*NPT + j] = far;
        float cx = xs[far], cy = ys[far], cz = zs[far];
        u64 ncx = pk(-cx,-cx), ncy = pk(-cy,-cy), ncz = pk(-cz,-cz);
        float bv = -1.0f; int bi = 0;
        #pragma unroll
        for (int q = 0; q < 4; q++) {
            u64 dx, dy, dz, s2;
            add2(dx, X[q], ncx);
            add2(dy, Y[q], ncy);
            add2(dz, Z[q], ncz);
            mul2(dx, dx, dx); mul2(dy, dy, dy); mul2(dz, dz, dz);
            add2(s2, dx, dy); add2(s2, s2, dz);
            float s0, s1, d0, d1;
            upk(s0, s1, s2); upk(d0, d1, D2[q]);
            d0 = fminf(d0, s0); d1 = fminf(d1, s1);
            D2[q] = pk(d0, d1);
            int i0 = tid + 1024*q, i1 = i0 + 512;
            if (d0 > bv) { bv = d0; bi = i0; }
            if (d1 > bv) { bv = d1; bi = i1; }
        }
        unsigned kv = ordf(bv);
        unsigned vmax = __reduce_max_sync(0xffffffffu, kv);
        unsigned iw = (kv == vmax) ? (unsigned)bi : 0xffffffffu;
        unsigned imin = __reduce_min_sync(0xffffffffu, iw);
        if (lane == 0)
            keys[(j & 1)*16 + w] = ((u64)vmax << 32) | (u64)(unsigned)(~imin);
        __syncthreads();
        // tree block-reduce over the 16 warp keys (depth 4 instead of 15-deep chain)
        const u64* kb = keys + (j & 1)*16;
        u64 v8[8];
        #pragma unroll
        for (int t = 0; t < 8; t++) {
            u64 a = kb[2*t], bq = kb[2*t + 1];
            v8[t] = a > bq ? a : bq;
        }
        u64 v4_0 = v8[0] > v8[1] ? v8[0] : v8[1];
        u64 v4_1 = v8[2] > v8[3] ? v8[2] : v8[3];
        u64 v4_2 = v8[4] > v8[5] ? v8[4] : v8[5];
        u64 v4_3 = v8[6] > v8[7] ? v8[6] : v8[7];
        u64 v2_0 = v4_0 > v4_1 ? v4_0 : v4_1;
        u64 v2_1 = v4_2 > v4_3 ? v4_2 : v4_3;
        u64 kk = v2_0 > v2_1 ? v2_0 : v2_1;
        far = (int)(~(unsigned)kk);
    }
}

// ---------------- ball query ----------------
__global__ void ball_kernel(const float* __restrict__ xyz, float* __restrict__ out) {
    extern __shared__ float sh[];
    float* xs = sh; float* ys = sh + NN; float* zs = sh + 2*NN; float* nn = sh + 3*NN;
    int blk = blockIdx.x, tid = threadIdx.x;
    int b = blk >> 3, cbase = (blk & 7) * 128;
    const float* xp = xyz + (size_t)b*NN*3;
    for (int t = tid; t < NN*3; t += 512) {
        float v = xp[t]; int i = t/3, c = t - 3*i;
        if (c == 0) xs[i] = v; else if (c == 1) ys[i] = v; else zs[i] = v;
    }
    __syncthreads();
    for (int i = tid; i < NN; i += 512)
        nn[i] = __fadd_rn(__fadd_rn(__fmul_rn(xs[i],xs[i]), __fmul_rn(ys[i],ys[i])), __fmul_rn(zs[i],zs[i]));
    __syncthreads();

    int w = tid >> 5, lane = tid & 31;
    const float r2 = 0.04f;
    for (int jj = w; jj < 128; jj += 16) {
        int j = cbase + jj;
        int fidx = g_fps[b*NPT + j];
        float cx = xs[fidx], cy = ys[fidx], cz = zs[fidx], cn = nn[fidx];
        if (lane == 0) {
            float* o = out + (size_t)(b*NPT + j)*3;
            o[0] = cx; o[1] = cy; o[2] = cz;
        }
        int cnt = 0, first = -1;
        int* bo = g_ball + (size_t)(b*NPT + j)*NSM;
        for (int base = 0; base < NN; base += 32) {
            int i = base + lane;
            float dot = __fadd_rn(__fadd_rn(__fmul_rn(cx,xs[i]), __fmul_rn(cy,ys[i])), __fmul_rn(cz,zs[i]));
            float sq  = __fadd_rn(__fadd_rn(__fmul_rn(-2.0f,dot), cn), nn[i]);
            bool ok = (sq <= r2);
            unsigned m = __ballot_sync(0xffffffffu, ok);
            if (first < 0 && m) first = base + __ffs(m) - 1;
            int pos = cnt + __popc(m & ((1u << lane) - 1u));
            if (ok && pos < NSM) bo[pos] = i;
            cnt += __popc(m);
            if (cnt >= NSM) break;
        }
        if (cnt < NSM && lane >= cnt) bo[lane] = first;
    }
}

// ============ tiled GEMM: thread = 16 samples (two 8-sample granules, +GOFF apart) x 8 ch ====
#define GEMM_LOOP(K, NWID, GOFF, AOFF_EXPR)                                    \
    u64 acc[8][8];                                                             \
    _Pragma("unroll")                                                          \
    for (int c = 0; c < 8; c++)                                                \
        _Pragma("unroll")                                                      \
        for (int p = 0; p < 8; p++) acc[c][p] = 0;                             \
    ulonglong2 a0v, a1v, b0v, b1v; float4 wq0, wq1;                            \
    {                                                                          \
        const int k = 0; int aoff = (AOFF_EXPR);                               \
        a0v = *(const ulonglong2*)(As + aoff);                                 \
        a1v = *(const ulonglong2*)(As + aoff + 4);                             \
        b0v = *(const ulonglong2*)(As + aoff + (GOFF));                        \
        b1v = *(const ulonglong2*)(As + aoff + (GOFF) + 4);                    \
        wq0 = *(const float4*)(Ws + tn*4);                                     \
        wq1 = *(const float4*)(Ws + (NWID)/2 + tn*4);                          \
    }                                                                          \
    _Pragma("unroll 2")                                                        \
    for (int kk = 0; kk < (K); kk++) {                                         \
        u64 a0 = a0v.x, a1 = a0v.y, a2 = a1v.x, a3 = a1v.y;                    \
        u64 a4 = b0v.x, a5 = b0v.y, a6 = b1v.x, a7 = b1v.y;                    \
        float wfv[8] = {wq0.x,wq0.y,wq0.z,wq0.w,wq1.x,wq1.y,wq1.z,wq1.w};      \
        if (kk + 1 < (K)) {                                                    \
            const int k = kk + 1; int aoff = (AOFF_EXPR);                      \
            a0v = *(const ulonglong2*)(As + aoff);                             \
            a1v = *(const ulonglong2*)(As + aoff + 4);                         \
            b0v = *(const ulonglong2*)(As + aoff + (GOFF));                    \
            b1v = *(const ulonglong2*)(As + aoff + (GOFF) + 4);                \
            wq0 = *(const float4*)(Ws + k*(NWID) + tn*4);                      \
            wq1 = *(const float4*)(Ws + k*(NWID) + (NWID)/2 + tn*4);           \
        }                                                                      \
        _Pragma("unroll")                                                      \
        for (int c = 0; c < 8; c++) {                                          \
            u64 wd = pk(wfv[c], wfv[c]);                                       \
            fma2(acc[c][0], wd, a0, acc[c][0]);                                \
            fma2(acc[c][1], wd, a1, acc[c][1]);                                \
            fma2(acc[c][2], wd, a2, acc[c][2]);                                \
            fma2(acc[c][3], wd, a3, acc[c][3]);                                \
            fma2(acc[c][4], wd, a4, acc[c][4]);                                \
            fma2(acc[c][5], wd, a5, acc[c][5]);                                \
            fma2(acc[c][6], wd, a6, acc[c][6]);                                \
            fma2(acc[c][7], wd, a7, acc[c][7]);                                \
        }                                                                      \
    }

// add bias + unpack 8 floats of one granule
#define EPI_GRANULE(c, P0, y)                                                  \
    upk(y[0],y[1],acc[c][P0+0]); upk(y[2],y[3],acc[c][P0+1]);                  \
    upk(y[4],y[5],acc[c][P0+2]); upk(y[6],y[7],acc[c][P0+3]);

// W interleaved position for channel n within a row of width NWID
__device__ __forceinline__ int wpos(int n, int nwid) {
    return ((n >> 2) & 1) * (nwid >> 1) + (n >> 3) * 4 + (n & 3);
}

// ---------------- conv1: cooperative gather + 67->64, M-tile 256, 128 thr ----------------
__global__ void __launch_bounds__(128, 2)
conv1_kernel(const float* __restrict__ xyz, const float* __restrict__ pts,
             const float* __restrict__ w1,  const float* __restrict__ b1,
             const float* __restrict__ nxyz) {
    extern __shared__ float sh[];
    float* As   = sh;              // 68*256 (rows k, swizzled 32B granules)
    float* Ws   = As + 68*256;     // 68*64 interleaved
    float* bs   = Ws + 68*64;
    float* ssum = bs + 64;
    float* ssq  = ssum + 64;
    int tid = threadIdx.x;
    for (int t = tid; t < 64*67; t += 128) { int n = t/67, k = t - n*67; Ws[k*64 + wpos(n,64)] = w1[t]; }
    if (tid < 64) { bs[tid] = b1[tid]; ssum[tid] = 0.f; ssq[tid] = 0.f; }

    int s0 = blockIdx.x*256;
    #pragma unroll
    for (int i = 0; i < 2; i++) {
        int m = tid + i*128;
        int s = s0 + m;
        int bj = s >> 5, b = s >> 15;
        int idx = g_ball[s];
        const float* xp = xyz  + (size_t)(b*NN + idx)*3;
        const float* cp = nxyz + (size_t)bj*3;
        As[0*256 + m] = xp[0]-cp[0];
        As[1*256 + m] = xp[1]-cp[1];
        As[2*256 + m] = xp[2]-cp[2];
    }
    {
        int w = tid >> 5, lane = tid & 31;
        int chunk = lane & 7, sg = lane >> 3;
        #pragma unroll
        for (int p = 0; p < 16; p++) {
            int sl = p*16 + w*4 + sg;
            int s = s0 + sl;
            int b = s >> 15;
            int idx = g_ball[s];
            const float4* pp = (const float4*)(pts + (size_t)(b*NN + idx)*64) + chunk*2;
            float4 v0 = pp[0], v1 = pp[1];
            int g = sl >> 3, slow = sl & 7;
            float vv[8] = {v0.x,v0.y,v0.z,v0.w,v1.x,v1.y,v1.z,v1.w};
            #pragma unroll
            for (int jj = 0; jj < 8; jj++) {
                int k = 3 + chunk*8 + jj;
                int gp = g ^ ((k >> 3) & 3);
                As[k*256 + gp*8 + slow] = vv[jj];
            }
        }
    }
    __syncthreads();

    int tn = tid & 7, tm = tid >> 3;       // tm 0..15: granules tm and tm+16
    int n0 = tn*8, m0 = tm*8;
    GEMM_LOOP(67, 64, 128, k*256 + ((tm ^ ((k>>3)&3)) << 3))

    int lane = tid & 31;
    float sn[8], qn[8];
    #pragma unroll
    for (int c = 0; c < 8; c++) {
        u64 bd = pk(bs[n0+c], bs[n0+c]);
        #pragma unroll
        for (int p = 0; p < 8; p++) add2(acc[c][p], acc[c][p], bd);
        float ya[8], yb[8];
        EPI_GRANULE(c, 0, ya)
        EPI_GRANULE(c, 4, yb)
        float sa = 0.f, qa = 0.f;
        #pragma unroll
        for (int i = 0; i < 8; i++) { sa += ya[i] + yb[i]; qa += ya[i]*ya[i] + yb[i]*yb[i]; }
        sn[c] = sa; qn[c] = qa;
        float* gp = g_y1 + (size_t)(n0+c)*TOT + s0 + m0;
        *(float4*)gp       = make_float4(ya[0],ya[1],ya[2],ya[3]);
        *(float4*)(gp+4)   = make_float4(ya[4],ya[5],ya[6],ya[7]);
        *(float4*)(gp+128) = make_float4(yb[0],yb[1],yb[2],yb[3]);
        *(float4*)(gp+132) = make_float4(yb[4],yb[5],yb[6],yb[7]);
    }
    #pragma unroll
    for (int off = 8; off <= 16; off <<= 1)
        #pragma unroll
        for (int c = 0; c < 8; c++) {
            sn[c] += __shfl_xor_sync(0xffffffffu, sn[c], off);
            qn[c] += __shfl_xor_sync(0xffffffffu, qn[c], off);
        }
    if (lane < 8) {
        #pragma unroll
        for (int c = 0; c < 8; c++) {
            atomicAdd(&ssum[n0+c], sn[c]);
            atomicAdd(&ssq[n0+c],  qn[c]);
        }
    }
    __syncthreads();
    if (tid < 64) {
        atomicAdd(&g_stats[tid],      ssum[tid]);
        atomicAdd(&g_stats[64 + tid], ssq[tid]);
    }
}

// ---------------- conv2: BN1 folded, 64->64, M-tile 256, 128 thr ----------------
__global__ void __launch_bounds__(128, 2)
conv2_kernel(const float* __restrict__ w2, const float* __restrict__ b2,
             const float* __restrict__ g1, const float* __restrict__ be1) {
    extern __shared__ float sh[];
    float* As   = sh;              // 64*256
    float* Ws   = As + 64*256;     // 64*64 interleaved
    float* sc   = Ws + 64*64;
    float* sf   = sc + 64;
    float* bs   = sf + 64;
    float* ssum = bs + 64;
    float* ssq  = ssum + 64;
    int tid = threadIdx.x;
    for (int t = tid; t < 64*64; t += 128) { int n = t >> 6, k = t & 63; Ws[k*64 + wpos(n,64)] = w2[t]; }
    if (tid < 64) {
        float s, h;
        bn_aff(g_stats[tid], g_stats[64 + tid], g1[tid], be1[tid], s, h);
        sc[tid] = s; sf[tid] = h;
        bs[tid] = b2[tid]; ssum[tid] = 0.f; ssq[tid] = 0.f;
    }
    __syncthreads();

    int s0 = blockIdx.x*256;
    {
        int col = (tid & 63) * 4, r0 = tid >> 6;
        #pragma unroll
        for (int r = r0; r < 64; r += 2) {
            float4 v = *(const float4*)(g_y1 + (size_t)r*TOT + s0 + col);
            float a = sc[r], b = sf[r];
            v.x = fmaxf(fmaf(v.x, a, b), 0.f);
            v.y = fmaxf(fmaf(v.y, a, b), 0.f);
            v.z = fmaxf(fmaf(v.z, a, b), 0.f);
            v.w = fmaxf(fmaf(v.w, a, b), 0.f);
            *(float4*)(As + r*256 + col) = v;
        }
    }
    __syncthreads();

    int tn = tid & 7, tm = tid >> 3;
    int n0 = tn*8, m0 = tm*8;
    GEMM_LOOP(64, 64, 128, k*256 + m0)

    int lane = tid & 31;
    float sn[8], qn[8];
    #pragma unroll
    for (int c = 0; c < 8; c++) {
        u64 bd = pk(bs[n0+c], bs[n0+c]);
        #pragma unroll
        for (int p = 0; p < 8; p++) add2(acc[c][p], acc[c][p], bd);
        float ya[8], yb[8];
        EPI_GRANULE(c, 0, ya)
        EPI_GRANULE(c, 4, yb)
        float sa = 0.f, qa = 0.f;
        #pragma unroll
        for (int i = 0; i < 8; i++) { sa += ya[i] + yb[i]; qa += ya[i]*ya[i] + yb[i]*yb[i]; }
        sn[c] = sa; qn[c] = qa;
        float* gp = g_y2 + (size_t)(n0+c)*TOT + s0 + m0;
        *(float4*)gp       = make_float4(ya[0],ya[1],ya[2],ya[3]);
        *(float4*)(gp+4)   = make_float4(ya[4],ya[5],ya[6],ya[7]);
        *(float4*)(gp+128) = make_float4(yb[0],yb[1],yb[2],yb[3]);
        *(float4*)(gp+132) = make_float4(yb[4],yb[5],yb[6],yb[7]);
    }
    #pragma unroll
    for (int off = 8; off <= 16; off <<= 1)
        #pragma unroll
        for (int c = 0; c < 8; c++) {
            sn[c] += __shfl_xor_sync(0xffffffffu, sn[c], off);
            qn[c] += __shfl_xor_sync(0xffffffffu, qn[c], off);
        }
    if (lane < 8) {
        #pragma unroll
        for (int c = 0; c < 8; c++) {
            atomicAdd(&ssum[n0+c], sn[c]);
            atomicAdd(&ssq[n0+c],  qn[c]);
        }
    }
    __syncthreads();
    if (tid < 64) {
        atomicAdd(&g_stats[128 + tid], ssum[tid]);
        atomicAdd(&g_stats[192 + tid], ssq[tid]);
    }
}

// ---------------- conv3: BN2 folded, 64->128, M-tile 128, N=128, 128 thr ----------------
__global__ void __launch_bounds__(128, 2)
conv3_kernel(const float* __restrict__ w3, const float* __restrict__ b3,
             const float* __restrict__ g2, const float* __restrict__ be2) {
    extern __shared__ float sh[];
    float* As   = sh;              // 64*128
    float* Ws   = As + 64*128;     // 64*128 interleaved
    float* sc   = Ws + 64*128;
    float* sf   = sc + 64;
    float* bs   = sf + 64;
    float* ssum = bs + 128;
    float* ssq  = ssum + 128;
    unsigned* smax = (unsigned*)(ssq + 128);   // 4 groups * 128 ch
    int tid = threadIdx.x;
    for (int t = tid; t < 128*64; t += 128) {
        int n = t >> 6, k = t & 63;
        Ws[k*128 + wpos(n,128)] = w3[t];
    }
    if (tid < 64)  {
        float s, h;
        bn_aff(g_stats[128 + tid], g_stats[192 + tid], g2[tid], be2[tid], s, h);
        sc[tid] = s; sf[tid] = h;
    }
    if (tid < 128) { bs[tid] = b3[tid]; ssum[tid] = 0.f; ssq[tid] = 0.f; }
    for (int t = tid; t < 512; t += 128) smax[t] = 0u;
    __syncthreads();

    int s0 = blockIdx.x*128;
    {
        int col = (tid & 31) * 4, r0 = tid >> 5;
        #pragma unroll
        for (int r = r0; r < 64; r += 4) {
            float4 v = *(const float4*)(g_y2 + (size_t)r*TOT + s0 + col);
            float a = sc[r], b = sf[r];
            v.x = fmaxf(fmaf(v.x, a, b), 0.f);
            v.y = fmaxf(fmaf(v.y, a, b), 0.f);
            v.z = fmaxf(fmaf(v.z, a, b), 0.f);
            v.w = fmaxf(fmaf(v.w, a, b), 0.f);
            *(float4*)(As + r*128 + col) = v;
        }
    }
    __syncthreads();

    int tn = tid & 15, tm = tid >> 4;      // tn 0..15 (128 ch), tm 0..7: granules tm, tm+8
    int n0 = tn*8, m0 = tm*8;
    GEMM_LOOP(64, 128, 64, k*128 + m0)

    int lane = tid & 31;
    int w = tid >> 5;
    int gA = w >> 1, gB = gA + 2;   // pool groups (32 samples) of the two granules
    float sn[8], qn[8], mxA[8], mxB[8];
    #pragma unroll
    for (int c = 0; c < 8; c++) {
        u64 bd = pk(bs[n0+c], bs[n0+c]);
        #pragma unroll
        for (int p = 0; p < 8; p++) add2(acc[c][p], acc[c][p], bd);
        float ya[8], yb[8];
        EPI_GRANULE(c, 0, ya)
        EPI_GRANULE(c, 4, yb)
        float sa = 0.f, qa = 0.f, ma = -1e30f, mb = -1e30f;
        #pragma unroll
        for (int i = 0; i < 8; i++) {
            sa += ya[i] + yb[i]; qa += ya[i]*ya[i] + yb[i]*yb[i];
            ma = fmaxf(ma, ya[i]); mb = fmaxf(mb, yb[i]);
        }
        sn[c] = sa; qn[c] = qa; mxA[c] = ma; mxB[c] = mb;
    }
    #pragma unroll
    for (int c = 0; c < 8; c++) {
        sn[c] += __shfl_xor_sync(0xffffffffu, sn[c], 16);
        qn[c] += __shfl_xor_sync(0xffffffffu, qn[c], 16);
        mxA[c] = fmaxf(mxA[c], __shfl_xor_sync(0xffffffffu, mxA[c], 16));
        mxB[c] = fmaxf(mxB[c], __shfl_xor_sync(0xffffffffu, mxB[c], 16));
    }
    if (lane < 16) {
        #pragma unroll
        for (int c = 0; c < 8; c++) {
            atomicAdd(&ssum[n0+c], sn[c]);
            atomicAdd(&ssq[n0+c],  qn[c]);
            atomicMax(&smax[gA*128 + n0 + c], ordf(mxA[c]));
            atomicMax(&smax[gB*128 + n0 + c], ordf(mxB[c]));
        }
    }
    __syncthreads();
    if (tid < 128) {
        atomicAdd(&g_stats[256 + tid], ssum[tid]);
        atomicAdd(&g_stats[384 + tid], ssq[tid]);
    }
    for (int t = tid; t < 512; t += 128) {
        int gg = t >> 7, n = t & 127;
        int bj = blockIdx.x*4 + gg;
        g_ymax[bj*128 + n] = unordf(smax[t]);
    }
}

// ---------------- output: BN3 folded (monotone affine + ReLU on per-channel max) ------------
__global__ void out_kernel(float* __restrict__ out,
                           const float* __restrict__ g3, const float* __restrict__ be3) {
    int i = blockIdx.x*blockDim.x + threadIdx.x;
    if (i < BB*NPT*128) {
        int c = i & 127;
        float s, h;
        bn_aff(g_stats[256 + c], g_stats[384 + c], g3[c], be3[c], s, h);
        float v = fmaf(g_ymax[i], s, h);
        out[BB*NPT*3 + i] = fmaxf(v, 0.0f);
    }
}

extern "C" void kernel_launch(void* const* d_in, const int* in_sizes, int n_in,
                              void* d_out, int out_size) {
    const float* xyz = (const float*)d_in[0];
    const float* pts = (const float*)d_in[1];
    const float* w1  = (const float*)d_in[2];
    const float* b1  = (const float*)d_in[3];
    const float* g1  = (const float*)d_in[4];
    const float* be1 = (const float*)d_in[5];
    const float* w2  = (const float*)d_in[6];
    const float* b2  = (const float*)d_in[7];
    const float* g2  = (const float*)d_in[8];
    const float* be2 = (const float*)d_in[9];
    const float* w3  = (const float*)d_in[10];
    const float* b3  = (const float*)d_in[11];
    const float* g3  = (const float*)d_in[12];
    const float* be3 = (const float*)d_in[13];
    float* out = (float*)d_out;

    const int FPS_SMEM   = 3*NN*4 + 32*8;
    const int BALL_SMEM  = 4*NN*4;
    const int CONV1_SMEM = (68*256 + 68*64 + 64*3)*4;
    const int CONV2_SMEM = (64*256 + 64*64 + 64*5)*4;
    const int CONV3_SMEM = (64*128 + 64*128 + 64*2 + 128*3 + 512)*4;

    cudaFuncSetAttribute(fps_kernel,   cudaFuncAttributeMaxDynamicSharedMemorySize, FPS_SMEM);
    cudaFuncSetAttribute(ball_kernel,  cudaFuncAttributeMaxDynamicSharedMemorySize, BALL_SMEM);
    cudaFuncSetAttribute(conv1_kernel, cudaFuncAttributeMaxDynamicSharedMemorySize, CONV1_SMEM);
    cudaFuncSetAttribute(conv2_kernel, cudaFuncAttributeMaxDynamicSharedMemorySize, CONV2_SMEM);
    cudaFuncSetAttribute(conv3_kernel, cudaFuncAttributeMaxDynamicSharedMemorySize, CONV3_SMEM);

    zero_stats_kernel<<<1, 512>>>();
    fps_kernel<<<BB, 512, FPS_SMEM>>>(xyz);
    ball_kernel<<<BB*8, 512, BALL_SMEM>>>(xyz, out);
    conv1_kernel<<<TOT/256, 128, CONV1_SMEM>>>(xyz, pts, w1, b1, out);
    conv2_kernel<<<TOT/256, 128, CONV2_SMEM>>>(w2, b2, g1, be1);
    conv3_kernel<<<TOT/128, 128, CONV3_SMEM>>>(w3, b3, g2, be2);
    out_kernel<<<(BB*NPT*128 + 255)/256, 256>>>(out, g3, be3);
}

// round 14
// speedup vs baseline: 1.1683x; 1.0654x over previous
#include <cuda_runtime.h>

#define BB   16
#define NN   4096
#define DD   64
#define NPT  1024
#define NSM  32
#define TOT  (BB*NPT*NSM)          // 524288 samples
#define CNT_INV (1.0f/524288.0f)

typedef unsigned long long u64;

// ---------------- f32x2 packed helpers ----------------
__device__ __forceinline__ u64 pk(float lo, float hi) {
    u64 r; asm("mov.b64 %0, {%1,%2};" : "=l"(r) : "f"(lo), "f"(hi)); return r;
}
__device__ __forceinline__ void upk(float& lo, float& hi, u64 v) {
    asm("mov.b64 {%0,%1}, %2;" : "=f"(lo), "=f"(hi) : "l"(v));
}
__device__ __forceinline__ void fma2(u64& d, u64 a, u64 b, u64 c) {
    asm("fma.rn.f32x2 %0, %1, %2, %3;" : "=l"(d) : "l"(a), "l"(b), "l"(c));
}
__device__ __forceinline__ void add2(u64& d, u64 a, u64 b) {
    asm("add.rn.f32x2 %0, %1, %2;" : "=l"(d) : "l"(a), "l"(b));
}
__device__ __forceinline__ void mul2(u64& d, u64 a, u64 b) {
    asm("mul.rn.f32x2 %0, %1, %2;" : "=l"(d) : "l"(a), "l"(b));
}

__device__ __forceinline__ unsigned ordf(float x) {
    unsigned u = __float_as_uint(x);
    return (u & 0x80000000u) ? ~u : (u | 0x80000000u);
}
__device__ __forceinline__ float unordf(unsigned u) {
    return (u & 0x80000000u) ? __uint_as_float(u & 0x7fffffffu) : __uint_as_float(~u);
}

// ---------------- device scratch ----------------
__device__ int   g_fps[BB*NPT];
__device__ int   g_ball[BB*NPT*NSM];
__device__ float g_y1[(size_t)64*TOT];   // [channel][sample]
__device__ float g_y2[(size_t)64*TOT];   // [channel][sample]
__device__ float g_ymax[BB*NPT*128];
__device__ float g_stats[512];           // L1 sum@0 sq@64 | L2 sum@128 sq@192 | L3 sum@256 sq@384

__global__ void zero_stats_kernel() {
    int t = threadIdx.x;
    if (t < 512) g_stats[t] = 0.0f;
}

__device__ __forceinline__ void bn_aff(float sum, float sq, float g, float beta,
                                       float& s, float& h) {
    float mean = sum * CNT_INV;
    float var  = sq  * CNT_INV - mean*mean;
    float inv  = rsqrtf(var + 1e-5f);
    s = g * inv;
    h = beta - mean*s;
}

// ---------------- FPS: 1 block/batch, 1 barrier/iter, redux argmax, tree block-reduce -------
__global__ void __launch_bounds__(512, 1)
fps_kernel(const float* __restrict__ xyz) {
    extern __shared__ float sh[];
    float* xs = sh; float* ys = sh + NN; float* zs = sh + 2*NN;
    u64* keys = (u64*)(sh + 3*NN);
    int b = blockIdx.x, tid = threadIdx.x, lane = tid & 31, w = tid >> 5;
    const float* xp = xyz + (size_t)b*NN*3;
    for (int t = tid; t < NN*3; t += 512) {
        float v = xp[t]; int i = t/3, c = t - 3*i;
        if (c == 0) xs[i] = v; else if (c == 1) ys[i] = v; else zs[i] = v;
    }
    __syncthreads();

    float px[8], py[8], pz[8];
    #pragma unroll
    for (int p = 0; p < 8; p++) {
        int i = tid + 512*p;
        px[p] = xs[i]; py[p] = ys[i]; pz[p] = zs[i];
    }
    u64 X[4], Y[4], Z[4], D2[4];
    #pragma unroll
    for (int q = 0; q < 4; q++) {
        X[q] = pk(px[2*q], px[2*q+1]);
        Y[q] = pk(py[2*q], py[2*q+1]);
        Z[q] = pk(pz[2*q], pz[2*q+1]);
        D2[q] = pk(1e10f, 1e10f);
    }

    int far = 0;
    for (int j = 0; j < NPT; j++) {
        if (tid == 0) g_fps[b*NPT + j] = far;
        float cx = xs[far], cy = ys[far], cz = zs[far];
        u64 ncx = pk(-cx,-cx), ncy = pk(-cy,-cy), ncz = pk(-cz,-cz);
        float bv = -1.0f; int bi = 0;
        #pragma unroll
        for (int q = 0; q < 4; q++) {
            u64 dx, dy, dz, s2;
            add2(dx, X[q], ncx);
            add2(dy, Y[q], ncy);
            add2(dz, Z[q], ncz);
            mul2(dx, dx, dx); mul2(dy, dy, dy); mul2(dz, dz, dz);
            add2(s2, dx, dy); add2(s2, s2, dz);
            float s0, s1, d0, d1;
            upk(s0, s1, s2); upk(d0, d1, D2[q]);
            d0 = fminf(d0, s0); d1 = fminf(d1, s1);
            D2[q] = pk(d0, d1);
            int i0 = tid + 1024*q, i1 = i0 + 512;
            if (d0 > bv) { bv = d0; bi = i0; }
            if (d1 > bv) { bv = d1; bi = i1; }
        }
        unsigned kv = ordf(bv);
        unsigned vmax = __reduce_max_sync(0xffffffffu, kv);
        unsigned iw = (kv == vmax) ? (unsigned)bi : 0xffffffffu;
        unsigned imin = __reduce_min_sync(0xffffffffu, iw);
        if (lane == 0)
            keys[(j & 1)*16 + w] = ((u64)vmax << 32) | (u64)(unsigned)(~imin);
        __syncthreads();
        const u64* kb = keys + (j & 1)*16;
        u64 v8[8];
        #pragma unroll
        for (int t = 0; t < 8; t++) {
            u64 a = kb[2*t], bq = kb[2*t + 1];
            v8[t] = a > bq ? a : bq;
        }
        u64 v4_0 = v8[0] > v8[1] ? v8[0] : v8[1];
        u64 v4_1 = v8[2] > v8[3] ? v8[2] : v8[3];
        u64 v4_2 = v8[4] > v8[5] ? v8[4] : v8[5];
        u64 v4_3 = v8[6] > v8[7] ? v8[6] : v8[7];
        u64 v2_0 = v4_0 > v4_1 ? v4_0 : v4_1;
        u64 v2_1 = v4_2 > v4_3 ? v4_2 : v4_3;
        u64 kk = v2_0 > v2_1 ? v2_0 : v2_1;
        far = (int)(~(unsigned)kk);
    }
}

// ---------------- ball query ----------------
__global__ void ball_kernel(const float* __restrict__ xyz, float* __restrict__ out) {
    extern __shared__ float sh[];
    float* xs = sh; float* ys = sh + NN; float* zs = sh + 2*NN; float* nn = sh + 3*NN;
    int blk = blockIdx.x, tid = threadIdx.x;
    int b = blk >> 3, cbase = (blk & 7) * 128;
    const float* xp = xyz + (size_t)b*NN*3;
    for (int t = tid; t < NN*3; t += 512) {
        float v = xp[t]; int i = t/3, c = t - 3*i;
        if (c == 0) xs[i] = v; else if (c == 1) ys[i] = v; else zs[i] = v;
    }
    __syncthreads();
    for (int i = tid; i < NN; i += 512)
        nn[i] = __fadd_rn(__fadd_rn(__fmul_rn(xs[i],xs[i]), __fmul_rn(ys[i],ys[i])), __fmul_rn(zs[i],zs[i]));
    __syncthreads();

    int w = tid >> 5, lane = tid & 31;
    const float r2 = 0.04f;
    for (int jj = w; jj < 128; jj += 16) {
        int j = cbase + jj;
        int fidx = g_fps[b*NPT + j];
        float cx = xs[fidx], cy = ys[fidx], cz = zs[fidx], cn = nn[fidx];
        if (lane == 0) {
            float* o = out + (size_t)(b*NPT + j)*3;
            o[0] = cx; o[1] = cy; o[2] = cz;
        }
        int cnt = 0, first = -1;
        int* bo = g_ball + (size_t)(b*NPT + j)*NSM;
        for (int base = 0; base < NN; base += 32) {
            int i = base + lane;
            float dot = __fadd_rn(__fadd_rn(__fmul_rn(cx,xs[i]), __fmul_rn(cy,ys[i])), __fmul_rn(cz,zs[i]));
            float sq  = __fadd_rn(__fadd_rn(__fmul_rn(-2.0f,dot), cn), nn[i]);
            bool ok = (sq <= r2);
            unsigned m = __ballot_sync(0xffffffffu, ok);
            if (first < 0 && m) first = base + __ffs(m) - 1;
            int pos = cnt + __popc(m & ((1u << lane) - 1u));
            if (ok && pos < NSM) bo[pos] = i;
            cnt += __popc(m);
            if (cnt >= NSM) break;
        }
        if (cnt < NSM && lane >= cnt) bo[lane] = first;
    }
}

// ======== uniform-W GEMM pass: warp = 8 channels (broadcast W), lane = 4 samples ========
// Per warp-k: A 1x LDS.128 (4 wf) + W 2x LDS.128 broadcast (2 wf) vs 16 fma2 -> fma-bound.
#define GEMM_PASS(K, NW, AOFF_EXPR)                                            \
    u64 acc[8][2];                                                             \
    _Pragma("unroll")                                                          \
    for (int c = 0; c < 8; c++) { acc[c][0] = 0; acc[c][1] = 0; }              \
    ulonglong2 av; float4 wq0, wq1;                                            \
    {                                                                          \
        const int k = 0;                                                       \
        av  = *(const ulonglong2*)(As + (AOFF_EXPR));                          \
        wq0 = *(const float4*)(Ws + n0);                                       \
        wq1 = *(const float4*)(Ws + n0 + 4);                                   \
    }                                                                          \
    _Pragma("unroll 4")                                                        \
    for (int kk = 0; kk < (K); kk++) {                                         \
        u64 a0 = av.x, a1 = av.y;                                              \
        float wfv[8] = {wq0.x,wq0.y,wq0.z,wq0.w,wq1.x,wq1.y,wq1.z,wq1.w};      \
        if (kk + 1 < (K)) {                                                    \
            const int k = kk + 1;                                              \
            av  = *(const ulonglong2*)(As + (AOFF_EXPR));                      \
            wq0 = *(const float4*)(Ws + k*(NW) + n0);                          \
            wq1 = *(const float4*)(Ws + k*(NW) + n0 + 4);                      \
        }                                                                      \
        _Pragma("unroll")                                                      \
        for (int c = 0; c < 8; c++) {                                          \
            u64 wd = pk(wfv[c], wfv[c]);                                       \
            fma2(acc[c][0], wd, a0, acc[c][0]);                                \
            fma2(acc[c][1], wd, a1, acc[c][1]);                                \
        }                                                                      \
    }

// ---------------- conv1: cooperative gather + 67->64, M-tile 128, 2 n-passes ----------------
__global__ void __launch_bounds__(128, 4)
conv1_kernel(const float* __restrict__ xyz, const float* __restrict__ pts,
             const float* __restrict__ w1,  const float* __restrict__ b1,
             const float* __restrict__ nxyz) {
    extern __shared__ float sh[];
    float* As   = sh;              // 68*128 (rows k, 32B granules XOR-swizzled)
    float* Ws   = As + 68*128;     // 68 rows x 68 (64 ch + pad4)
    float* bs   = Ws + 68*68;
    float* ssum = bs + 64;
    float* ssq  = ssum + 64;
    int tid = threadIdx.x;
    for (int t = tid; t < 64*67; t += 128) { int n = t/67, k = t - n*67; Ws[k*68 + n] = w1[t]; }
    if (tid < 64) { bs[tid] = b1[tid]; ssum[tid] = 0.f; ssq[tid] = 0.f; }

    int s0 = blockIdx.x*128;
    {   // rows 0..2: one thread per sample (sw=0 for k<8, so unswizzled is consistent)
        int s = s0 + tid;
        int bj = s >> 5, b = s >> 15;
        int idx = g_ball[s];
        const float* xp = xyz  + (size_t)(b*NN + idx)*3;
        const float* cp = nxyz + (size_t)bj*3;
        As[0*128 + tid] = xp[0]-cp[0];
        As[1*128 + tid] = xp[1]-cp[1];
        As[2*128 + tid] = xp[2]-cp[2];
    }
    {   // rows 3..66: 8 threads/sample, 32B contiguous each, XOR-swizzled STS
        int w = tid >> 5, lane = tid & 31;
        int chunk = lane & 7, sg = lane >> 3;
        #pragma unroll
        for (int p = 0; p < 8; p++) {
            int sl = p*16 + w*4 + sg;
            int s = s0 + sl;
            int b = s >> 15;
            int idx = g_ball[s];
            const float4* pp = (const float4*)(pts + (size_t)(b*NN + idx)*64) + chunk*2;
            float4 v0 = pp[0], v1 = pp[1];
            int g = sl >> 3, slow = sl & 7;
            float vv[8] = {v0.x,v0.y,v0.z,v0.w,v1.x,v1.y,v1.z,v1.w};
            #pragma unroll
            for (int jj = 0; jj < 8; jj++) {
                int k = 3 + chunk*8 + jj;
                int gp = g ^ ((k >> 3) & 3);
                As[k*128 + gp*8 + slow] = vv[jj];
            }
        }
    }
    __syncthreads();

    int lane = tid & 31, wid = tid >> 5;
    int m0 = lane*4;
    #pragma unroll 1
    for (int pass = 0; pass < 2; pass++) {
        int n0 = wid*8 + pass*32;
        GEMM_PASS(67, 68,
            k*128 + ((((lane>>1) ^ ((k>>3)&3)) << 3) + ((lane&1) << 2)))

        float sn[8], qn[8];
        #pragma unroll
        for (int c = 0; c < 8; c++) {
            u64 bd = pk(bs[n0+c], bs[n0+c]);
            add2(acc[c][0], acc[c][0], bd);
            add2(acc[c][1], acc[c][1], bd);
            float y0,y1,y2,y3;
            upk(y0,y1,acc[c][0]); upk(y2,y3,acc[c][1]);
            sn[c] = (y0+y1)+(y2+y3);
            qn[c] = y0*y0+y1*y1+y2*y2+y3*y3;
            float* gp = g_y1 + (size_t)(n0+c)*TOT + s0 + m0;
            *(float4*)gp = make_float4(y0,y1,y2,y3);
        }
        #pragma unroll
        for (int off = 1; off <= 16; off <<= 1)
            #pragma unroll
            for (int c = 0; c < 8; c++) {
                sn[c] += __shfl_xor_sync(0xffffffffu, sn[c], off);
                qn[c] += __shfl_xor_sync(0xffffffffu, qn[c], off);
            }
        if (lane == 0) {
            #pragma unroll
            for (int c = 0; c < 8; c++) {
                atomicAdd(&ssum[n0+c], sn[c]);
                atomicAdd(&ssq[n0+c],  qn[c]);
            }
        }
    }
    __syncthreads();
    if (tid < 64) {
        atomicAdd(&g_stats[tid],      ssum[tid]);
        atomicAdd(&g_stats[64 + tid], ssq[tid]);
    }
}

// ---------------- conv2: BN1 folded, 64->64, M-tile 128, 2 n-passes ----------------
__global__ void __launch_bounds__(128, 4)
conv2_kernel(const float* __restrict__ w2, const float* __restrict__ b2,
             const float* __restrict__ g1, const float* __restrict__ be1) {
    extern __shared__ float sh[];
    float* As   = sh;              // 64*128
    float* Ws   = As + 64*128;     // 64 rows x 68
    float* sc   = Ws + 64*68;
    float* sf   = sc + 64;
    float* bs   = sf + 64;
    float* ssum = bs + 64;
    float* ssq  = ssum + 64;
    int tid = threadIdx.x;
    for (int t = tid; t < 64*64; t += 128) { int n = t >> 6, k = t & 63; Ws[k*68 + n] = w2[t]; }
    if (tid < 64) {
        float s, h;
        bn_aff(g_stats[tid], g_stats[64 + tid], g1[tid], be1[tid], s, h);
        sc[tid] = s; sf[tid] = h;
        bs[tid] = b2[tid]; ssum[tid] = 0.f; ssq[tid] = 0.f;
    }
    __syncthreads();

    int s0 = blockIdx.x*128;
    {
        int col = (tid & 31) * 4, r0 = tid >> 5;
        #pragma unroll
        for (int r = r0; r < 64; r += 4) {
            float4 v = *(const float4*)(g_y1 + (size_t)r*TOT + s0 + col);
            float a = sc[r], b = sf[r];
            v.x = fmaxf(fmaf(v.x, a, b), 0.f);
            v.y = fmaxf(fmaf(v.y, a, b), 0.f);
            v.z = fmaxf(fmaf(v.z, a, b), 0.f);
            v.w = fmaxf(fmaf(v.w, a, b), 0.f);
            *(float4*)(As + r*128 + col) = v;
        }
    }
    __syncthreads();

    int lane = tid & 31, wid = tid >> 5;
    int m0 = lane*4;
    #pragma unroll 1
    for (int pass = 0; pass < 2; pass++) {
        int n0 = wid*8 + pass*32;
        GEMM_PASS(64, 68, k*128 + m0)

        float sn[8], qn[8];
        #pragma unroll
        for (int c = 0; c < 8; c++) {
            u64 bd = pk(bs[n0+c], bs[n0+c]);
            add2(acc[c][0], acc[c][0], bd);
            add2(acc[c][1], acc[c][1], bd);
            float y0,y1,y2,y3;
            upk(y0,y1,acc[c][0]); upk(y2,y3,acc[c][1]);
            sn[c] = (y0+y1)+(y2+y3);
            qn[c] = y0*y0+y1*y1+y2*y2+y3*y3;
            float* gp = g_y2 + (size_t)(n0+c)*TOT + s0 + m0;
            *(float4*)gp = make_float4(y0,y1,y2,y3);
        }
        #pragma unroll
        for (int off = 1; off <= 16; off <<= 1)
            #pragma unroll
            for (int c = 0; c < 8; c++) {
                sn[c] += __shfl_xor_sync(0xffffffffu, sn[c], off);
                qn[c] += __shfl_xor_sync(0xffffffffu, qn[c], off);
            }
        if (lane == 0) {
            #pragma unroll
            for (int c = 0; c < 8; c++) {
                atomicAdd(&ssum[n0+c], sn[c]);
                atomicAdd(&ssq[n0+c],  qn[c]);
            }
        }
    }
    __syncthreads();
    if (tid < 64) {
        atomicAdd(&g_stats[128 + tid], ssum[tid]);
        atomicAdd(&g_stats[192 + tid], ssq[tid]);
    }
}

// ---------------- conv3: BN2 folded, 64->128, M-tile 128, 4 n-passes, maxpool ----------------
__global__ void __launch_bounds__(128, 3)
conv3_kernel(const float* __restrict__ w3, const float* __restrict__ b3,
             const float* __restrict__ g2, const float* __restrict__ be2) {
    extern __shared__ float sh[];
    float* As   = sh;              // 64*128
    float* Ws   = As + 64*128;     // 64 rows x 132 (128 ch + pad4)
    float* sc   = Ws + 64*132;
    float* sf   = sc + 64;
    float* bs   = sf + 64;         // 128
    float* ssum = bs + 128;        // 128
    float* ssq  = ssum + 128;      // 128
    unsigned* smax = (unsigned*)(ssq + 128);   // 4 groups * 128 ch
    int tid = threadIdx.x;
    for (int t = tid; t < 128*64; t += 128) {
        int n = t >> 6, k = t & 63;
        Ws[k*132 + n] = w3[t];
    }
    if (tid < 64)  {
        float s, h;
        bn_aff(g_stats[128 + tid], g_stats[192 + tid], g2[tid], be2[tid], s, h);
        sc[tid] = s; sf[tid] = h;
    }
    if (tid < 128) { bs[tid] = b3[tid]; ssum[tid] = 0.f; ssq[tid] = 0.f; }
    for (int t = tid; t < 512; t += 128) smax[t] = 0u;
    __syncthreads();

    int s0 = blockIdx.x*128;
    {
        int col = (tid & 31) * 4, r0 = tid >> 5;
        #pragma unroll
        for (int r = r0; r < 64; r += 4) {
            float4 v = *(const float4*)(g_y2 + (size_t)r*TOT + s0 + col);
            float a = sc[r], b = sf[r];
            v.x = fmaxf(fmaf(v.x, a, b), 0.f);
            v.y = fmaxf(fmaf(v.y, a, b), 0.f);
            v.z = fmaxf(fmaf(v.z, a, b), 0.f);
            v.w = fmaxf(fmaf(v.w, a, b), 0.f);
            *(float4*)(As + r*128 + col) = v;
        }
    }
    __syncthreads();

    int lane = tid & 31, wid = tid >> 5;
    int m0 = lane*4;
    int g = lane >> 3;             // pool group of 32 samples (lanes 8-aligned)
    #pragma unroll 1
    for (int pass = 0; pass < 4; pass++) {
        int n0 = wid*8 + pass*32;
        GEMM_PASS(64, 132, k*128 + m0)

        float sn[8], qn[8], mx[8];
        #pragma unroll
        for (int c = 0; c < 8; c++) {
            u64 bd = pk(bs[n0+c], bs[n0+c]);
            add2(acc[c][0], acc[c][0], bd);
            add2(acc[c][1], acc[c][1], bd);
            float y0,y1,y2,y3;
            upk(y0,y1,acc[c][0]); upk(y2,y3,acc[c][1]);
            sn[c] = (y0+y1)+(y2+y3);
            qn[c] = y0*y0+y1*y1+y2*y2+y3*y3;
            mx[c] = fmaxf(fmaxf(y0,y1), fmaxf(y2,y3));
        }
        #pragma unroll
        for (int off = 1; off <= 16; off <<= 1)
            #pragma unroll
            for (int c = 0; c < 8; c++) {
                sn[c] += __shfl_xor_sync(0xffffffffu, sn[c], off);
                qn[c] += __shfl_xor_sync(0xffffffffu, qn[c], off);
            }
        #pragma unroll
        for (int off = 1; off <= 4; off <<= 1)
            #pragma unroll
            for (int c = 0; c < 8; c++)
                mx[c] = fmaxf(mx[c], __shfl_xor_sync(0xffffffffu, mx[c], off));
        if (lane == 0) {
            #pragma unroll
            for (int c = 0; c < 8; c++) {
                atomicAdd(&ssum[n0+c], sn[c]);
                atomicAdd(&ssq[n0+c],  qn[c]);
            }
        }
        if ((lane & 7) == 0) {
            #pragma unroll
            for (int c = 0; c < 8; c++)
                atomicMax(&smax[g*128 + n0 + c], ordf(mx[c]));
        }
    }
    __syncthreads();
    if (tid < 128) {
        atomicAdd(&g_stats[256 + tid], ssum[tid]);
        atomicAdd(&g_stats[384 + tid], ssq[tid]);
    }
    for (int t = tid; t < 512; t += 128) {
        int gg = t >> 7, n = t & 127;
        int bj = blockIdx.x*4 + gg;
        g_ymax[bj*128 + n] = unordf(smax[t]);
    }
}

// ---------------- output: BN3 folded (monotone affine + ReLU on per-channel max) ------------
__global__ void out_kernel(float* __restrict__ out,
                           const float* __restrict__ g3, const float* __restrict__ be3) {
    int i = blockIdx.x*blockDim.x + threadIdx.x;
    if (i < BB*NPT*128) {
        int c = i & 127;
        float s, h;
        bn_aff(g_stats[256 + c], g_stats[384 + c], g3[c], be3[c], s, h);
        float v = fmaf(g_ymax[i], s, h);
        out[BB*NPT*3 + i] = fmaxf(v, 0.0f);
    }
}

extern "C" void kernel_launch(void* const* d_in, const int* in_sizes, int n_in,
                              void* d_out, int out_size) {
    const float* xyz = (const float*)d_in[0];
    const float* pts = (const float*)d_in[1];
    const float* w1  = (const float*)d_in[2];
    const float* b1  = (const float*)d_in[3];
    const float* g1  = (const float*)d_in[4];
    const float* be1 = (const float*)d_in[5];
    const float* w2  = (const float*)d_in[6];
    const float* b2  = (const float*)d_in[7];
    const float* g2  = (const float*)d_in[8];
    const float* be2 = (const float*)d_in[9];
    const float* w3  = (const float*)d_in[10];
    const float* b3  = (const float*)d_in[11];
    const float* g3  = (const float*)d_in[12];
    const float* be3 = (const float*)d_in[13];
    float* out = (float*)d_out;

    const int FPS_SMEM   = 3*NN*4 + 32*8;
    const int BALL_SMEM  = 4*NN*4;
    const int CONV1_SMEM = (68*128 + 68*68 + 64*3)*4;               // ~54 KB -> 4 CTAs
    const int CONV2_SMEM = (64*128 + 64*68 + 64*5)*4;               // ~51 KB -> 4 CTAs
    const int CONV3_SMEM = (64*128 + 64*132 + 64*2 + 128*3 + 512)*4;// ~70 KB -> 3 CTAs

    cudaFuncSetAttribute(fps_kernel,   cudaFuncAttributeMaxDynamicSharedMemorySize, FPS_SMEM);
    cudaFuncSetAttribute(ball_kernel,  cudaFuncAttributeMaxDynamicSharedMemorySize, BALL_SMEM);
    cudaFuncSetAttribute(conv1_kernel, cudaFuncAttributeMaxDynamicSharedMemorySize, CONV1_SMEM);
    cudaFuncSetAttribute(conv2_kernel, cudaFuncAttributeMaxDynamicSharedMemorySize, CONV2_SMEM);
    cudaFuncSetAttribute(conv3_kernel, cudaFuncAttributeMaxDynamicSharedMemorySize, CONV3_SMEM);

    zero_stats_kernel<<<1, 512>>>();
    fps_kernel<<<BB, 512, FPS_SMEM>>>(xyz);
    ball_kernel<<<BB*8, 512, BALL_SMEM>>>(xyz, out);
    conv1_kernel<<<TOT/128, 128, CONV1_SMEM>>>(xyz, pts, w1, b1, out);
    conv2_kernel<<<TOT/128, 128, CONV2_SMEM>>>(w2, b2, g1, be1);
    conv3_kernel<<<TOT/128, 128, CONV3_SMEM>>>(w3, b3, g2, be2);
    out_kernel<<<(BB*NPT*128 + 255)/256, 256>>>(out, g3, be3);
}

// round 16
// speedup vs baseline: 1.1757x; 1.0064x over previous
#include <cuda_runtime.h>

#define BB   16
#define NN   4096
#define DD   64
#define NPT  1024
#define NSM  32
#define TOT  (BB*NPT*NSM)          // 524288 samples
#define CNT_INV (1.0f/524288.0f)

typedef unsigned long long u64;

// ---------------- f32x2 packed helpers ----------------
__device__ __forceinline__ u64 pk(float lo, float hi) {
    u64 r; asm("mov.b64 %0, {%1,%2};" : "=l"(r) : "f"(lo), "f"(hi)); return r;
}
__device__ __forceinline__ void upk(float& lo, float& hi, u64 v) {
    asm("mov.b64 {%0,%1}, %2;" : "=f"(lo), "=f"(hi) : "l"(v));
}
__device__ __forceinline__ void fma2(u64& d, u64 a, u64 b, u64 c) {
    asm("fma.rn.f32x2 %0, %1, %2, %3;" : "=l"(d) : "l"(a), "l"(b), "l"(c));
}
__device__ __forceinline__ void add2(u64& d, u64 a, u64 b) {
    asm("add.rn.f32x2 %0, %1, %2;" : "=l"(d) : "l"(a), "l"(b));
}
__device__ __forceinline__ void mul2(u64& d, u64 a, u64 b) {
    asm("mul.rn.f32x2 %0, %1, %2;" : "=l"(d) : "l"(a), "l"(b));
}

__device__ __forceinline__ unsigned ordf(float x) {
    unsigned u = __float_as_uint(x);
    return (u & 0x80000000u) ? ~u : (u | 0x80000000u);
}
__device__ __forceinline__ float unordf(unsigned u) {
    return (u & 0x80000000u) ? __uint_as_float(u & 0x7fffffffu) : __uint_as_float(~u);
}

// ---------------- device scratch ----------------
__device__ int   g_fps[BB*NPT];
__device__ int   g_ball[BB*NPT*NSM];
__device__ float g_y1[(size_t)64*TOT];   // [channel][sample]
__device__ float g_y2[(size_t)64*TOT];   // [channel][sample]
__device__ float g_ymax[BB*NPT*128];
__device__ float g_stats[512];           // L1 sum@0 sq@64 | L2 sum@128 sq@192 | L3 sum@256 sq@384

__global__ void zero_stats_kernel() {
    int t = threadIdx.x;
    if (t < 512) g_stats[t] = 0.0f;
}

__device__ __forceinline__ void bn_aff(float sum, float sq, float g, float beta,
                                       float& s, float& h) {
    float mean = sum * CNT_INV;
    float var  = sq  * CNT_INV - mean*mean;
    float inv  = rsqrtf(var + 1e-5f);
    s = g * inv;
    h = beta - mean*s;
}

// ---------------- FPS: 1 block/batch, 1 barrier/iter, redux argmax, tree block-reduce -------
__global__ void __launch_bounds__(512, 1)
fps_kernel(const float* __restrict__ xyz) {
    extern __shared__ float sh[];
    float* xs = sh; float* ys = sh + NN; float* zs = sh + 2*NN;
    u64* keys = (u64*)(sh + 3*NN);
    int b = blockIdx.x, tid = threadIdx.x, lane = tid & 31, w = tid >> 5;
    const float* xp = xyz + (size_t)b*NN*3;
    for (int t = tid; t < NN*3; t += 512) {
        float v = xp[t]; int i = t/3, c = t - 3*i;
        if (c == 0) xs[i] = v; else if (c == 1) ys[i] = v; else zs[i] = v;
    }
    __syncthreads();

    float px[8], py[8], pz[8];
    #pragma unroll
    for (int p = 0; p < 8; p++) {
        int i = tid + 512*p;
        px[p] = xs[i]; py[p] = ys[i]; pz[p] = zs[i];
    }
    u64 X[4], Y[4], Z[4], D2[4];
    #pragma unroll
    for (int q = 0; q < 4; q++) {
        X[q] = pk(px[2*q], px[2*q+1]);
        Y[q] = pk(py[2*q], py[2*q+1]);
        Z[q] = pk(pz[2*q], pz[2*q+1]);
        D2[q] = pk(1e10f, 1e10f);
    }

    int far = 0;
    for (int j = 0; j < NPT; j++) {
        if (tid == 0) g_fps[b*NPT + j] = far;
        float cx = xs[far], cy = ys[far], cz = zs[far];
        u64 ncx = pk(-cx,-cx), ncy = pk(-cy,-cy), ncz = pk(-cz,-cz);
        float bv = -1.0f; int bi = 0;
        #pragma unroll
        for (int q = 0; q < 4; q++) {
            u64 dx, dy, dz, s2;
            add2(dx, X[q], ncx);
            add2(dy, Y[q], ncy);
            add2(dz, Z[q], ncz);
            mul2(dx, dx, dx); mul2(dy, dy, dy); mul2(dz, dz, dz);
            add2(s2, dx, dy); add2(s2, s2, dz);
            float s0, s1, d0, d1;
            upk(s0, s1, s2); upk(d0, d1, D2[q]);
            d0 = fminf(d0, s0); d1 = fminf(d1, s1);
            D2[q] = pk(d0, d1);
            int i0 = tid + 1024*q, i1 = i0 + 512;
            if (d0 > bv) { bv = d0; bi = i0; }
            if (d1 > bv) { bv = d1; bi = i1; }
        }
        unsigned kv = ordf(bv);
        unsigned vmax = __reduce_max_sync(0xffffffffu, kv);
        unsigned iw = (kv == vmax) ? (unsigned)bi : 0xffffffffu;
        unsigned imin = __reduce_min_sync(0xffffffffu, iw);
        if (lane == 0)
            keys[(j & 1)*16 + w] = ((u64)vmax << 32) | (u64)(unsigned)(~imin);
        __syncthreads();
        const u64* kb = keys + (j & 1)*16;
        u64 v8[8];
        #pragma unroll
        for (int t = 0; t < 8; t++) {
            u64 a = kb[2*t], bq = kb[2*t + 1];
            v8[t] = a > bq ? a : bq;
        }
        u64 v4_0 = v8[0] > v8[1] ? v8[0] : v8[1];
        u64 v4_1 = v8[2] > v8[3] ? v8[2] : v8[3];
        u64 v4_2 = v8[4] > v8[5] ? v8[4] : v8[5];
        u64 v4_3 = v8[6] > v8[7] ? v8[6] : v8[7];
        u64 v2_0 = v4_0 > v4_1 ? v4_0 : v4_1;
        u64 v2_1 = v4_2 > v4_3 ? v4_2 : v4_3;
        u64 kk = v2_0 > v2_1 ? v2_0 : v2_1;
        far = (int)(~(unsigned)kk);
    }
}

// ---------------- ball query ----------------
__global__ void ball_kernel(const float* __restrict__ xyz, float* __restrict__ out) {
    extern __shared__ float sh[];
    float* xs = sh; float* ys = sh + NN; float* zs = sh + 2*NN; float* nn = sh + 3*NN;
    int blk = blockIdx.x, tid = threadIdx.x;
    int b = blk >> 3, cbase = (blk & 7) * 128;
    const float* xp = xyz + (size_t)b*NN*3;
    for (int t = tid; t < NN*3; t += 512) {
        float v = xp[t]; int i = t/3, c = t - 3*i;
        if (c == 0) xs[i] = v; else if (c == 1) ys[i] = v; else zs[i] = v;
    }
    __syncthreads();
    for (int i = tid; i < NN; i += 512)
        nn[i] = __fadd_rn(__fadd_rn(__fmul_rn(xs[i],xs[i]), __fmul_rn(ys[i],ys[i])), __fmul_rn(zs[i],zs[i]));
    __syncthreads();

    int w = tid >> 5, lane = tid & 31;
    const float r2 = 0.04f;
    for (int jj = w; jj < 128; jj += 16) {
        int j = cbase + jj;
        int fidx = g_fps[b*NPT + j];
        float cx = xs[fidx], cy = ys[fidx], cz = zs[fidx], cn = nn[fidx];
        if (lane == 0) {
            float* o = out + (size_t)(b*NPT + j)*3;
            o[0] = cx; o[1] = cy; o[2] = cz;
        }
        int cnt = 0, first = -1;
        int* bo = g_ball + (size_t)(b*NPT + j)*NSM;
        for (int base = 0; base < NN; base += 32) {
            int i = base + lane;
            float dot = __fadd_rn(__fadd_rn(__fmul_rn(cx,xs[i]), __fmul_rn(cy,ys[i])), __fmul_rn(cz,zs[i]));
            float sq  = __fadd_rn(__fadd_rn(__fmul_rn(-2.0f,dot), cn), nn[i]);
            bool ok = (sq <= r2);
            unsigned m = __ballot_sync(0xffffffffu, ok);
            if (first < 0 && m) first = base + __ffs(m) - 1;
            int pos = cnt + __popc(m & ((1u << lane) - 1u));
            if (ok && pos < NSM) bo[pos] = i;
            cnt += __popc(m);
            if (cnt >= NSM) break;
        }
        if (cnt < NSM && lane >= cnt) bo[lane] = first;
    }
}

// ======== uniform-W GEMM: warp = 16 channels (broadcast W), lane = 4 samples ========
// Per warp-k: A 1x LDS.128 (4 wf) + W 4x LDS.128 broadcast (4 wf) vs 32 fma2 -> fma-bound
// with 50% LDS headroom and halved per-fma issue overhead.
#define GEMM_PASS16(K, NW, AOFF_EXPR)                                          \
    u64 acc[16][2];                                                            \
    _Pragma("unroll")                                                          \
    for (int c = 0; c < 16; c++) { acc[c][0] = 0; acc[c][1] = 0; }             \
    ulonglong2 av; float4 wq0, wq1, wq2, wq3;                                  \
    {                                                                          \
        const int k = 0;                                                       \
        av  = *(const ulonglong2*)(As + (AOFF_EXPR));                          \
        wq0 = *(const float4*)(Ws + n0);                                       \
        wq1 = *(const float4*)(Ws + n0 + 4);                                   \
        wq2 = *(const float4*)(Ws + n0 + 8);                                   \
        wq3 = *(const float4*)(Ws + n0 + 12);                                  \
    }                                                                          \
    _Pragma("unroll 2")                                                        \
    for (int kk = 0; kk < (K); kk++) {                                         \
        u64 a0 = av.x, a1 = av.y;                                              \
        float wfv[16] = {wq0.x,wq0.y,wq0.z,wq0.w, wq1.x,wq1.y,wq1.z,wq1.w,     \
                         wq2.x,wq2.y,wq2.z,wq2.w, wq3.x,wq3.y,wq3.z,wq3.w};    \
        if (kk + 1 < (K)) {                                                    \
            const int k = kk + 1;                                              \
            av  = *(const ulonglong2*)(As + (AOFF_EXPR));                      \
            wq0 = *(const float4*)(Ws + k*(NW) + n0);                          \
            wq1 = *(const float4*)(Ws + k*(NW) + n0 + 4);                      \
            wq2 = *(const float4*)(Ws + k*(NW) + n0 + 8);                      \
            wq3 = *(const float4*)(Ws + k*(NW) + n0 + 12);                     \
        }                                                                      \
        _Pragma("unroll")                                                      \
        for (int c = 0; c < 16; c++) {                                         \
            u64 wd = pk(wfv[c], wfv[c]);                                       \
            fma2(acc[c][0], wd, a0, acc[c][0]);                                \
            fma2(acc[c][1], wd, a1, acc[c][1]);                                \
        }                                                                      \
    }

// ---------------- conv1: cooperative gather + 67->64, M-tile 128, single n-pass -------------
__global__ void __launch_bounds__(128, 3)
conv1_kernel(const float* __restrict__ xyz, const float* __restrict__ pts,
             const float* __restrict__ w1,  const float* __restrict__ b1,
             const float* __restrict__ nxyz) {
    extern __shared__ float sh[];
    float* As   = sh;              // 68*128 (rows k, 32B granules XOR-swizzled)
    float* Ws   = As + 68*128;     // 68 rows x 68 (64 ch + pad4)
    float* bs   = Ws + 68*68;
    float* ssum = bs + 64;
    float* ssq  = ssum + 64;
    int tid = threadIdx.x;
    for (int t = tid; t < 64*67; t += 128) { int n = t/67, k = t - n*67; Ws[k*68 + n] = w1[t]; }
    if (tid < 64) { bs[tid] = b1[tid]; ssum[tid] = 0.f; ssq[tid] = 0.f; }

    int s0 = blockIdx.x*128;
    {   // rows 0..2: one thread per sample (sw=0 for k<8, so unswizzled is consistent)
        int s = s0 + tid;
        int bj = s >> 5, b = s >> 15;
        int idx = g_ball[s];
        const float* xp = xyz  + (size_t)(b*NN + idx)*3;
        const float* cp = nxyz + (size_t)bj*3;
        As[0*128 + tid] = xp[0]-cp[0];
        As[1*128 + tid] = xp[1]-cp[1];
        As[2*128 + tid] = xp[2]-cp[2];
    }
    {   // rows 3..66: 8 threads/sample, 32B contiguous each, XOR-swizzled STS
        int w = tid >> 5, lane = tid & 31;
        int chunk = lane & 7, sg = lane >> 3;
        #pragma unroll
        for (int p = 0; p < 8; p++) {
            int sl = p*16 + w*4 + sg;
            int s = s0 + sl;
            int b = s >> 15;
            int idx = g_ball[s];
            const float4* pp = (const float4*)(pts + (size_t)(b*NN + idx)*64) + chunk*2;
            float4 v0 = pp[0], v1 = pp[1];
            int g = sl >> 3, slow = sl & 7;
            float vv[8] = {v0.x,v0.y,v0.z,v0.w,v1.x,v1.y,v1.z,v1.w};
            #pragma unroll
            for (int jj = 0; jj < 8; jj++) {
                int k = 3 + chunk*8 + jj;
                int gp = g ^ ((k >> 3) & 3);
                As[k*128 + gp*8 + slow] = vv[jj];
            }
        }
    }
    __syncthreads();

    int lane = tid & 31, wid = tid >> 5;
    int m0 = lane*4;
    int n0 = wid*16;
    GEMM_PASS16(67, 68,
        k*128 + ((((lane>>1) ^ ((k>>3)&3)) << 3) + ((lane&1) << 2)))

    float sn[16], qn[16];
    #pragma unroll
    for (int c = 0; c < 16; c++) {
        u64 bd = pk(bs[n0+c], bs[n0+c]);
        add2(acc[c][0], acc[c][0], bd);
        add2(acc[c][1], acc[c][1], bd);
        float y0,y1,y2,y3;
        upk(y0,y1,acc[c][0]); upk(y2,y3,acc[c][1]);
        sn[c] = (y0+y1)+(y2+y3);
        qn[c] = y0*y0+y1*y1+y2*y2+y3*y3;
        float* gp = g_y1 + (size_t)(n0+c)*TOT + s0 + m0;
        *(float4*)gp = make_float4(y0,y1,y2,y3);
    }
    #pragma unroll
    for (int off = 1; off <= 16; off <<= 1)
        #pragma unroll
        for (int c = 0; c < 16; c++) {
            sn[c] += __shfl_xor_sync(0xffffffffu, sn[c], off);
            qn[c] += __shfl_xor_sync(0xffffffffu, qn[c], off);
        }
    if (lane == 0) {
        #pragma unroll
        for (int c = 0; c < 16; c++) {
            atomicAdd(&ssum[n0+c], sn[c]);
            atomicAdd(&ssq[n0+c],  qn[c]);
        }
    }
    __syncthreads();
    if (tid < 64) {
        atomicAdd(&g_stats[tid],      ssum[tid]);
        atomicAdd(&g_stats[64 + tid], ssq[tid]);
    }
}

// ---------------- conv2: BN1 folded, 64->64, M-tile 128, single n-pass ----------------
__global__ void __launch_bounds__(128, 3)
conv2_kernel(const float* __restrict__ w2, const float* __restrict__ b2,
             const float* __restrict__ g1, const float* __restrict__ be1) {
    extern __shared__ float sh[];
    float* As   = sh;              // 64*128
    float* Ws   = As + 64*128;     // 64 rows x 68
    float* sc   = Ws + 64*68;
    float* sf   = sc + 64;
    float* bs   = sf + 64;
    float* ssum = bs + 64;
    float* ssq  = ssum + 64;
    int tid = threadIdx.x;
    for (int t = tid; t < 64*64; t += 128) { int n = t >> 6, k = t & 63; Ws[k*68 + n] = w2[t]; }
    if (tid < 64) {
        float s, h;
        bn_aff(g_stats[tid], g_stats[64 + tid], g1[tid], be1[tid], s, h);
        sc[tid] = s; sf[tid] = h;
        bs[tid] = b2[tid]; ssum[tid] = 0.f; ssq[tid] = 0.f;
    }
    __syncthreads();

    int s0 = blockIdx.x*128;
    {
        int col = (tid & 31) * 4, r0 = tid >> 5;
        #pragma unroll
        for (int r = r0; r < 64; r += 4) {
            float4 v = *(const float4*)(g_y1 + (size_t)r*TOT + s0 + col);
            float a = sc[r], b = sf[r];
            v.x = fmaxf(fmaf(v.x, a, b), 0.f);
            v.y = fmaxf(fmaf(v.y, a, b), 0.f);
            v.z = fmaxf(fmaf(v.z, a, b), 0.f);
            v.w = fmaxf(fmaf(v.w, a, b), 0.f);
            *(float4*)(As + r*128 + col) = v;
        }
    }
    __syncthreads();

    int lane = tid & 31, wid = tid >> 5;
    int m0 = lane*4;
    int n0 = wid*16;
    GEMM_PASS16(64, 68, k*128 + m0)

    float sn[16], qn[16];
    #pragma unroll
    for (int c = 0; c < 16; c++) {
        u64 bd = pk(bs[n0+c], bs[n0+c]);
        add2(acc[c][0], acc[c][0], bd);
        add2(acc[c][1], acc[c][1], bd);
        float y0,y1,y2,y3;
        upk(y0,y1,acc[c][0]); upk(y2,y3,acc[c][1]);
        sn[c] = (y0+y1)+(y2+y3);
        qn[c] = y0*y0+y1*y1+y2*y2+y3*y3;
        float* gp = g_y2 + (size_t)(n0+c)*TOT + s0 + m0;
        *(float4*)gp = make_float4(y0,y1,y2,y3);
    }
    #pragma unroll
    for (int off = 1; off <= 16; off <<= 1)
        #pragma unroll
        for (int c = 0; c < 16; c++) {
            sn[c] += __shfl_xor_sync(0xffffffffu, sn[c], off);
            qn[c] += __shfl_xor_sync(0xffffffffu, qn[c], off);
        }
    if (lane == 0) {
        #pragma unroll
        for (int c = 0; c < 16; c++) {
            atomicAdd(&ssum[n0+c], sn[c]);
            atomicAdd(&ssq[n0+c],  qn[c]);
        }
    }
    __syncthreads();
    if (tid < 64) {
        atomicAdd(&g_stats[128 + tid], ssum[tid]);
        atomicAdd(&g_stats[192 + tid], ssq[tid]);
    }
}

// ---------------- conv3: BN2 folded, 64->128, M-tile 128, 2 n-passes, maxpool ----------------
__global__ void __launch_bounds__(128, 3)
conv3_kernel(const float* __restrict__ w3, const float* __restrict__ b3,
             const float* __restrict__ g2, const float* __restrict__ be2) {
    extern __shared__ float sh[];
    float* As   = sh;              // 64*128
    float* Ws   = As + 64*128;     // 64 rows x 132 (128 ch + pad4)
    float* sc   = Ws + 64*132;
    float* sf   = sc + 64;
    float* bs   = sf + 64;         // 128
    float* ssum = bs + 128;        // 128
    float* ssq  = ssum + 128;      // 128
    unsigned* smax = (unsigned*)(ssq + 128);   // 4 groups * 128 ch
    int tid = threadIdx.x;
    for (int t = tid; t < 128*64; t += 128) {
        int n = t >> 6, k = t & 63;
        Ws[k*132 + n] = w3[t];
    }
    if (tid < 64)  {
        float s, h;
        bn_aff(g_stats[128 + tid], g_stats[192 + tid], g2[tid], be2[tid], s, h);
        sc[tid] = s; sf[tid] = h;
    }
    if (tid < 128) { bs[tid] = b3[tid]; ssum[tid] = 0.f; ssq[tid] = 0.f; }
    for (int t = tid; t < 512; t += 128) smax[t] = 0u;
    __syncthreads();

    int s0 = blockIdx.x*128;
    {
        int col = (tid & 31) * 4, r0 = tid >> 5;
        #pragma unroll
        for (int r = r0; r < 64; r += 4) {
            float4 v = *(const float4*)(g_y2 + (size_t)r*TOT + s0 + col);
            float a = sc[r], b = sf[r];
            v.x = fmaxf(fmaf(v.x, a, b), 0.f);
            v.y = fmaxf(fmaf(v.y, a, b), 0.f);
            v.z = fmaxf(fmaf(v.z, a, b), 0.f);
            v.w = fmaxf(fmaf(v.w, a, b), 0.f);
            *(float4*)(As + r*128 + col) = v;
        }
    }
    __syncthreads();

    int lane = tid & 31, wid = tid >> 5;
    int m0 = lane*4;
    int g = lane >> 3;             // pool group of 32 samples (lanes 8-aligned)
    #pragma unroll 1
    for (int pass = 0; pass < 2; pass++) {
        int n0 = wid*16 + pass*64;
        GEMM_PASS16(64, 132, k*128 + m0)

        float sn[16], qn[16], mx[16];
        #pragma unroll
        for (int c = 0; c < 16; c++) {
            u64 bd = pk(bs[n0+c], bs[n0+c]);
            add2(acc[c][0], acc[c][0], bd);
            add2(acc[c][1], acc[c][1], bd);
            float y0,y1,y2,y3;
            upk(y0,y1,acc[c][0]); upk(y2,y3,acc[c][1]);
            sn[c] = (y0+y1)+(y2+y3);
            qn[c] = y0*y0+y1*y1+y2*y2+y3*y3;
            mx[c] = fmaxf(fmaxf(y0,y1), fmaxf(y2,y3));
        }
        #pragma unroll
        for (int off = 1; off <= 16; off <<= 1)
            #pragma unroll
            for (int c = 0; c < 16; c++) {
                sn[c] += __shfl_xor_sync(0xffffffffu, sn[c], off);
                qn[c] += __shfl_xor_sync(0xffffffffu, qn[c], off);
            }
        #pragma unroll
        for (int off = 1; off <= 4; off <<= 1)
            #pragma unroll
            for (int c = 0; c < 16; c++)
                mx[c] = fmaxf(mx[c], __shfl_xor_sync(0xffffffffu, mx[c], off));
        if (lane == 0) {
            #pragma unroll
            for (int c = 0; c < 16; c++) {
                atomicAdd(&ssum[n0+c], sn[c]);
                atomicAdd(&ssq[n0+c],  qn[c]);
            }
        }
        if ((lane & 7) == 0) {
            #pragma unroll
            for (int c = 0; c < 16; c++)
                atomicMax(&smax[g*128 + n0 + c], ordf(mx[c]));
        }
    }
    __syncthreads();
    if (tid < 128) {
        atomicAdd(&g_stats[256 + tid], ssum[tid]);
        atomicAdd(&g_stats[384 + tid], ssq[tid]);
    }
    for (int t = tid; t < 512; t += 128) {
        int gg = t >> 7, n = t & 127;
        int bj = blockIdx.x*4 + gg;
        g_ymax[bj*128 + n] = unordf(smax[t]);
    }
}

// ---------------- output: BN3 folded (monotone affine + ReLU on per-channel max) ------------
__global__ void out_kernel(float* __restrict__ out,
                           const float* __restrict__ g3, const float* __restrict__ be3) {
    int i = blockIdx.x*blockDim.x + threadIdx.x;
    if (i < BB*NPT*128) {
        int c = i & 127;
        float s, h;
        bn_aff(g_stats[256 + c], g_stats[384 + c], g3[c], be3[c], s, h);
        float v = fmaf(g_ymax[i], s, h);
        out[BB*NPT*3 + i] = fmaxf(v, 0.0f);
    }
}

extern "C" void kernel_launch(void* const* d_in, const int* in_sizes, int n_in,
                              void* d_out, int out_size) {
    const float* xyz = (const float*)d_in[0];
    const float* pts = (const float*)d_in[1];
    const float* w1  = (const float*)d_in[2];
    const float* b1  = (const float*)d_in[3];
    const float* g1  = (const float*)d_in[4];
    const float* be1 = (const float*)d_in[5];
    const float* w2  = (const float*)d_in[6];
    const float* b2  = (const float*)d_in[7];
    const float* g2  = (const float*)d_in[8];
    const float* be2 = (const float*)d_in[9];
    const float* w3  = (const float*)d_in[10];
    const float* b3  = (const float*)d_in[11];
    const float* g3  = (const float*)d_in[12];
    const float* be3 = (const float*)d_in[13];
    float* out = (float*)d_out;

    const int FPS_SMEM   = 3*NN*4 + 32*8;
    const int BALL_SMEM  = 4*NN*4;
    const int CONV1_SMEM = (68*128 + 68*68 + 64*3)*4;               // ~54 KB
    const int CONV2_SMEM = (64*128 + 64*68 + 64*5)*4;               // ~51 KB
    const int CONV3_SMEM = (64*128 + 64*132 + 64*2 + 128*3 + 512)*4;// ~70 KB

    cudaFuncSetAttribute(fps_kernel,   cudaFuncAttributeMaxDynamicSharedMemorySize, FPS_SMEM);
    cudaFuncSetAttribute(ball_kernel,  cudaFuncAttributeMaxDynamicSharedMemorySize, BALL_SMEM);
    cudaFuncSetAttribute(conv1_kernel, cudaFuncAttributeMaxDynamicSharedMemorySize, CONV1_SMEM);
    cudaFuncSetAttribute(conv2_kernel, cudaFuncAttributeMaxDynamicSharedMemorySize, CONV2_SMEM);
    cudaFuncSetAttribute(conv3_kernel, cudaFuncAttributeMaxDynamicSharedMemorySize, CONV3_SMEM);

    zero_stats_kernel<<<1, 512>>>();
    fps_kernel<<<BB, 512, FPS_SMEM>>>(xyz);
    ball_kernel<<<BB*8, 512, BALL_SMEM>>>(xyz, out);
    conv1_kernel<<<TOT/128, 128, CONV1_SMEM>>>(xyz, pts, w1, b1, out);
    conv2_kernel<<<TOT/128, 128, CONV2_SMEM>>>(w2, b2, g1, be1);
    conv3_kernel<<<TOT/128, 128, CONV3_SMEM>>>(w3, b3, g2, be2);
    out_kernel<<<(BB*NPT*128 + 255)/256, 256>>>(out, g3, be3);
}